// round 12
// baseline (speedup 1.0000x reference)
#include <cuda_runtime.h>
#include <cuda_fp16.h>
#include <math.h>
#include <stdint.h>

// ---------------------------------------------------------------------------
// SingleHeadAttentionInference B=4, S=4096, D=1024 fp32.
// fp16 mma.sync GEMMs (fp32 acc), 128x128x32 tiles, 8 warps x (32x64).
// Software-pipelined: register double-buffered fragments + 5-stage smem
// pipeline with ONE wait_group/__syncthreads per TWO k-chunks (64 MMAs).
// Softmax fused into scores epilogue; PV epilogue reduces partials+normalizes.
// ---------------------------------------------------------------------------

#define BATCH 4
#define SEQ   4096
#define DIM   1024
#define TOK   (BATCH*SEQ)
#define SCALE 0.03125f

// ---- scratch ----
__device__ __half g_x  [(size_t)TOK*DIM];
__device__ __half g_q  [(size_t)TOK*DIM];
__device__ __half g_k  [(size_t)TOK*DIM];
__device__ __half g_vt [(size_t)TOK*DIM];             // v^T per batch [b][d][s]
__device__ __half g_c  [(size_t)TOK*DIM];             // 32*ctx
__device__ __half g_e  [(size_t)BATCH*SEQ*SEQ];       // exp(scores), unnormalized
__device__ __half g_w  [4][DIM*DIM];                  // Wq,Wk,Wv,Wo
__device__ float  g_part[(size_t)TOK*32];             // per-(row, nblock) exp sums

// ---------------------------------------------------------------------------
// helpers
// ---------------------------------------------------------------------------
__device__ __forceinline__ uint32_t s2u(const void* p) {
    uint32_t a;
    asm("{ .reg .u64 t; cvta.to.shared.u64 t, %1; cvt.u32.u64 %0, t; }"
        : "=r"(a) : "l"(p));
    return a;
}
__device__ __forceinline__ void cp16(uint32_t s, const void* g) {
    asm volatile("cp.async.cg.shared.global [%0], [%1], 16;" :: "r"(s), "l"(g));
}
__device__ __forceinline__ void ldsm4(uint32_t& r0, uint32_t& r1,
                                      uint32_t& r2, uint32_t& r3, uint32_t a) {
    asm volatile("ldmatrix.sync.aligned.m8n8.x4.shared.b16 {%0,%1,%2,%3}, [%4];"
                 : "=r"(r0), "=r"(r1), "=r"(r2), "=r"(r3) : "r"(a));
}
__device__ __forceinline__ void mma_f16(float* c, const uint32_t* a, const uint32_t* b) {
    asm volatile(
        "mma.sync.aligned.m16n8k16.row.col.f32.f16.f16.f32 "
        "{%0,%1,%2,%3}, {%4,%5,%6,%7}, {%8,%9}, {%0,%1,%2,%3};"
        : "+f"(c[0]), "+f"(c[1]), "+f"(c[2]), "+f"(c[3])
        : "r"(a[0]), "r"(a[1]), "r"(a[2]), "r"(a[3]), "r"(b[0]), "r"(b[1]));
}
__device__ __forceinline__ __half2 h2(float a, float b) {
    __half2 u; u.x = __float2half_rn(a); u.y = __float2half_rn(b); return u;
}

// tile geometry: 128x128 block, BK=32, 80B pitch (conflict-free ldmatrix)
#define ROWP    80
#define TILE_B  (128*ROWP)
#define STAGE_B (2*TILE_B)
#define STAGES  5
#define SMEMSZ  (STAGES*STAGE_B)  // 102400
#define NTHREADS 256

#define STAGE_LOAD(stg_, kc_) do {                                            \
    const size_t k0_ = (size_t)(kc_) << 5;                                    \
    _Pragma("unroll")                                                         \
    for (int j_ = 0; j_ < 4; j_++) {                                          \
        int id_  = tid + j_ * NTHREADS;                                       \
        int t_   = id_ >> 9;                                                  \
        int id2_ = id_ & 511;                                                 \
        int row_ = id2_ >> 2;                                                 \
        int ch_  = id2_ & 3;                                                  \
        uint32_t sa_ = sb + (uint32_t)(stg_) * STAGE_B + (uint32_t)t_ * TILE_B\
                     + (uint32_t)row_ * ROWP + (uint32_t)ch_ * 16;            \
        const __half* src_ = (t_ == 0) ? A : B;                               \
        size_t gr_ = (t_ == 0) ? (bm + row_) : (bn + row_);                   \
        cp16(sa_, src_ + gr_ * (size_t)K + k0_ + ch_ * 8);                    \
    }                                                                         \
    asm volatile("cp.async.commit_group;" ::: "memory");                      \
} while (0)

// load one kk-half's fragments from a stage base into frag buffer fb
#define FRAG_LOAD(fb_, stbase_, kkoff_) do {                                  \
    _Pragma("unroll")                                                         \
    for (int mt_ = 0; mt_ < 2; ++mt_) {                                       \
        uint32_t ba_ = (stbase_) + aOff + (uint32_t)mt_ * (16 * ROWP) + (kkoff_);\
        ldsm4(aF[fb_][mt_][0], aF[fb_][mt_][1], aF[fb_][mt_][2], aF[fb_][mt_][3], ba_);\
    }                                                                         \
    _Pragma("unroll")                                                         \
    for (int ng_ = 0; ng_ < 4; ++ng_) {                                       \
        uint32_t bb_ = (stbase_) + TILE_B + bOff + (uint32_t)ng_ * (16 * ROWP) + (kkoff_);\
        uint32_t r0_, r1_, r2_, r3_;                                          \
        ldsm4(r0_, r1_, r2_, r3_, bb_);                                       \
        bF[fb_][2*ng_][0] = r0_;  bF[fb_][2*ng_+1][0] = r1_;                  \
        bF[fb_][2*ng_][1] = r2_;  bF[fb_][2*ng_+1][1] = r3_;                  \
    }                                                                         \
} while (0)

#define MMA16(fb_) do {                                                       \
    _Pragma("unroll")                                                         \
    for (int mt_ = 0; mt_ < 2; ++mt_)                                         \
        _Pragma("unroll")                                                     \
        for (int nt_ = 0; nt_ < 8; ++nt_)                                     \
            mma_f16(acc[mt_][nt_], aF[fb_][mt_], bF[fb_][nt_]);               \
} while (0)

// ---------------------------------------------------------------------------
// GEMM modes:
//   0 = fp32 out + bias p0
//   4 = fused qkv: cols<1024->q, <2048->k, else v^T; biases p0/p1/p2
//   5 = E-scores: exp(alpha*acc) fp16 + row partial sums -> part
//   6 = ctx: acc * alpha / rowsum(part) -> fp16   (reduces part in-kernel)
// ---------------------------------------------------------------------------
template<int OUT>
__global__ __launch_bounds__(NTHREADS, 2)
void mma_gemm(const __half* __restrict__ A, const __half* __restrict__ B,
              const float* __restrict__ p0, const float* __restrict__ p1,
              const float* __restrict__ p2,
              void* __restrict__ O0, void* __restrict__ O1, void* __restrict__ O2,
              float* __restrict__ part,
              int K, int ldC, float alpha,
              long long sA, long long sB, long long sC)
{
    extern __shared__ char smem[];
    const uint32_t sb = s2u(smem);
    const int tid  = threadIdx.x;
    const int lane = tid & 31;
    const int wid  = tid >> 5;
    const int bz   = blockIdx.z;
    const size_t bm = (size_t)blockIdx.y * 128;
    const size_t bn = (size_t)blockIdx.x * 128;

    A += (size_t)bz * sA;  B += (size_t)bz * sB;

    const int wm = (wid & 3) * 32;
    const int wn = (wid >> 2) * 64;

    const int lrow = (lane & 7) + ((lane >> 3) & 1) * 8;
    const uint32_t lkc = (uint32_t)((lane >> 4) & 1) * 16;
    const uint32_t aOff = (uint32_t)(wm + lrow) * ROWP + lkc;
    const uint32_t bOff = (uint32_t)(wn + lrow) * ROWP + lkc;

    float acc[2][8][4];
#pragma unroll
    for (int i = 0; i < 2; i++)
#pragma unroll
        for (int j = 0; j < 8; j++)
#pragma unroll
            for (int r = 0; r < 4; r++) acc[i][j][r] = 0.0f;

    const int nk = K >> 5;   // always even and >= 4 at every call site

    // prologue: 3 stages in flight, all complete before first pair
    STAGE_LOAD(0, 0);
    STAGE_LOAD(1, 1);
    STAGE_LOAD(2, 2);
    asm volatile("cp.async.wait_group 0;" ::: "memory");
    __syncthreads();

    uint32_t aF[2][2][4], bF[2][8][2];
    FRAG_LOAD(0, sb, 0u);                          // stage0 kk0

    for (int kc = 0; kc < nk; kc += 2) {
        const int n1 = kc + 3, n2 = kc + 4;
        if (n1 < nk) STAGE_LOAD(n1 % STAGES, n1);
        else asm volatile("cp.async.commit_group;" ::: "memory");
        if (n2 < nk) STAGE_LOAD(n2 % STAGES, n2);
        else asm volatile("cp.async.commit_group;" ::: "memory");

        const uint32_t st0 = sb + (uint32_t)(kc % STAGES) * STAGE_B;
        const uint32_t st1 = sb + (uint32_t)((kc + 1) % STAGES) * STAGE_B;

        FRAG_LOAD(1, st0, 32u);      // kc kk1
        MMA16(0);                    // kc kk0
        FRAG_LOAD(0, st1, 0u);       // kc+1 kk0
        MMA16(1);                    // kc kk1
        FRAG_LOAD(1, st1, 32u);      // kc+1 kk1
        MMA16(0);                    // kc+1 kk0
        MMA16(1);                    // kc+1 kk1

        asm volatile("cp.async.wait_group 1;" ::: "memory");  // stages <= kc+3 done
        __syncthreads();

        if (kc + 2 < nk) {
            const uint32_t st2 = sb + (uint32_t)((kc + 2) % STAGES) * STAGE_B;
            FRAG_LOAD(0, st2, 0u);   // next pair's kk0 (stage certified done)
        }
    }

    // ---- epilogue ----
    const int gid = lane >> 2, tig = lane & 3;

    if (OUT == 0) {
#pragma unroll
        for (int mt = 0; mt < 2; ++mt) {
            const size_t r0 = bm + wm + mt * 16 + gid;
#pragma unroll
            for (int nt = 0; nt < 8; ++nt) {
                const size_t c = bn + wn + nt * 8 + tig * 2;
                float b0 = p0[c], b1 = p0[c + 1];
                float* o = (float*)O0 + (size_t)bz * sC;
                float2 u0; u0.x = acc[mt][nt][0] * alpha + b0;
                           u0.y = acc[mt][nt][1] * alpha + b1;
                float2 u1; u1.x = acc[mt][nt][2] * alpha + b0;
                           u1.y = acc[mt][nt][3] * alpha + b1;
                *(float2*)(o + r0 * (size_t)ldC + c)       = u0;
                *(float2*)(o + (r0 + 8) * (size_t)ldC + c) = u1;
            }
        }
    } else if (OUT == 4) {
        const int sel = (int)(bn >> 10);           // 0=q,1=k,2=v
        const int cb  = (int)(bn & 1023);
        const float* bias = (sel == 0) ? p0 : (sel == 1) ? p1 : p2;
#pragma unroll
        for (int mt = 0; mt < 2; ++mt) {
            const size_t r0 = bm + wm + mt * 16 + gid;
#pragma unroll
            for (int nt = 0; nt < 8; ++nt) {
                const int lc = cb + wn + nt * 8 + tig * 2;
                float b0 = bias[lc], b1 = bias[lc + 1];
                float v00 = acc[mt][nt][0] + b0, v01 = acc[mt][nt][1] + b1;
                float v10 = acc[mt][nt][2] + b0, v11 = acc[mt][nt][3] + b1;
                if (sel < 2) {
                    __half* o = (sel == 0) ? (__half*)O0 : (__half*)O1;
                    *(__half2*)(o + r0 * (size_t)DIM + lc)       = h2(v00, v01);
                    *(__half2*)(o + (r0 + 8) * (size_t)DIM + lc) = h2(v10, v11);
                } else {
                    const int b = (int)(r0 >> 12);
                    const int s0 = (int)(r0 & 4095);
                    __half* o = (__half*)O2 + (size_t)b * DIM * SEQ;
                    o[(size_t)lc * SEQ + s0]           = __float2half_rn(v00);
                    o[(size_t)(lc + 1) * SEQ + s0]     = __float2half_rn(v01);
                    o[(size_t)lc * SEQ + s0 + 8]       = __float2half_rn(v10);
                    o[(size_t)(lc + 1) * SEQ + s0 + 8] = __float2half_rn(v11);
                }
            }
        }
    } else if (OUT == 5) {
        float ps[2][2] = {{0.f, 0.f}, {0.f, 0.f}};
#pragma unroll
        for (int mt = 0; mt < 2; ++mt) {
            const size_t r0 = bm + wm + mt * 16 + gid;
#pragma unroll
            for (int nt = 0; nt < 8; ++nt) {
                const size_t c = bn + wn + nt * 8 + tig * 2;
                float e00 = __expf(fminf(acc[mt][nt][0] * alpha, 11.0f));
                float e01 = __expf(fminf(acc[mt][nt][1] * alpha, 11.0f));
                float e10 = __expf(fminf(acc[mt][nt][2] * alpha, 11.0f));
                float e11 = __expf(fminf(acc[mt][nt][3] * alpha, 11.0f));
                __half* o = (__half*)O0 + (size_t)bz * sC;
                *(__half2*)(o + r0 * (size_t)ldC + c)       = h2(e00, e01);
                *(__half2*)(o + (r0 + 8) * (size_t)ldC + c) = h2(e10, e11);
                ps[mt][0] += e00 + e01;
                ps[mt][1] += e10 + e11;
            }
        }
#pragma unroll
        for (int mt = 0; mt < 2; ++mt)
#pragma unroll
            for (int sr = 0; sr < 2; ++sr) {
                float v = ps[mt][sr];
                v += __shfl_xor_sync(0xffffffffu, v, 1);
                v += __shfl_xor_sync(0xffffffffu, v, 2);
                ps[mt][sr] = v;
            }
        __syncthreads();
        float* buf = (float*)smem;            // [128 rows][2 n-halves]
        if (tig == 0) {
            const int half = wid >> 2;
            buf[(wm + gid) * 2 + half]           = ps[0][0];
            buf[(wm + gid + 8) * 2 + half]       = ps[0][1];
            buf[(wm + 16 + gid) * 2 + half]      = ps[1][0];
            buf[(wm + 16 + gid + 8) * 2 + half]  = ps[1][1];
        }
        __syncthreads();
        if (tid < 128) {
            float t = buf[tid * 2] + buf[tid * 2 + 1];
            part[((size_t)bz * SEQ + bm + tid) * 32 + blockIdx.x] = t;
        }
    } else {  // OUT == 6: reduce part -> inv in smem, then normalize
        __syncthreads();                       // mainloop smem free
        float* invb = (float*)smem;            // [128]
        if (tid < 128) {
            const float* pp = part + ((size_t)bz * SEQ + bm + tid) * 32;
            float s = 0.0f;
#pragma unroll
            for (int j = 0; j < 32; j++) s += pp[j];
            invb[tid] = 1.0f / s;
        }
        __syncthreads();
#pragma unroll
        for (int mt = 0; mt < 2; ++mt) {
            const int lr0 = wm + mt * 16 + gid;
            const size_t r0 = bm + lr0;
            const float i0 = invb[lr0]     * alpha;
            const float i1 = invb[lr0 + 8] * alpha;
#pragma unroll
            for (int nt = 0; nt < 8; ++nt) {
                const size_t c = bn + wn + nt * 8 + tig * 2;
                __half* o = (__half*)O0 + (size_t)bz * sC;
                *(__half2*)(o + r0 * (size_t)ldC + c) =
                    h2(acc[mt][nt][0] * i0, acc[mt][nt][1] * i0);
                *(__half2*)(o + (r0 + 8) * (size_t)ldC + c) =
                    h2(acc[mt][nt][2] * i1, acc[mt][nt][3] * i1);
            }
        }
    }
}

// ---------------------------------------------------------------------------
// fused casts: y=0 -> x, y>0 -> weights
// ---------------------------------------------------------------------------
__global__ void cast_all_kernel(const float* __restrict__ x,
                                const float* __restrict__ w0, const float* __restrict__ w1,
                                const float* __restrict__ w2, const float* __restrict__ w3,
                                __half* __restrict__ xh, __half* __restrict__ wh)
{
    const int y = blockIdx.y;
    const float* s;
    __half* d;
    int n4;
    if (y == 0) { s = x;  d = xh; n4 = TOK * DIM / 4; }
    else {
        s = (y == 1) ? w0 : (y == 2) ? w1 : (y == 3) ? w2 : w3;
        d = wh + (size_t)(y - 1) * DIM * DIM;
        n4 = DIM * DIM / 4;
    }
    for (int i = blockIdx.x * blockDim.x + threadIdx.x; i < n4;
         i += gridDim.x * blockDim.x) {
        float4 v = ((const float4*)s)[i];
        ((__half2*)d)[i*2+0] = h2(v.x, v.y);
        ((__half2*)d)[i*2+1] = h2(v.z, v.w);
    }
}

// ---------------------------------------------------------------------------
// launch
// ---------------------------------------------------------------------------
extern "C" void kernel_launch(void* const* d_in, const int* in_sizes, int n_in,
                              void* d_out, int out_size)
{
    const float* x  = (const float*)d_in[0];
    const float* Wq = (const float*)d_in[1];
    const float* bq = (const float*)d_in[2];
    const float* Wk = (const float*)d_in[3];
    const float* bk = (const float*)d_in[4];
    const float* Wv = (const float*)d_in[5];
    const float* bv = (const float*)d_in[6];
    const float* Wo = (const float*)d_in[7];
    const float* bo = (const float*)d_in[8];
    float* out = (float*)d_out;

    __half *xh, *qh, *kh, *vth, *ch, *eh, *w;
    float *part;
    cudaGetSymbolAddress((void**)&xh,   g_x);
    cudaGetSymbolAddress((void**)&qh,   g_q);
    cudaGetSymbolAddress((void**)&kh,   g_k);
    cudaGetSymbolAddress((void**)&vth,  g_vt);
    cudaGetSymbolAddress((void**)&ch,   g_c);
    cudaGetSymbolAddress((void**)&eh,   g_e);
    cudaGetSymbolAddress((void**)&w,    g_w);
    cudaGetSymbolAddress((void**)&part, g_part);

    cudaFuncSetAttribute(mma_gemm<0>, cudaFuncAttributeMaxDynamicSharedMemorySize, SMEMSZ);
    cudaFuncSetAttribute(mma_gemm<4>, cudaFuncAttributeMaxDynamicSharedMemorySize, SMEMSZ);
    cudaFuncSetAttribute(mma_gemm<5>, cudaFuncAttributeMaxDynamicSharedMemorySize, SMEMSZ);
    cudaFuncSetAttribute(mma_gemm<6>, cudaFuncAttributeMaxDynamicSharedMemorySize, SMEMSZ);

    const long long sX = (long long)SEQ * DIM;
    const long long sT = (long long)DIM * SEQ;
    const long long sS = (long long)SEQ * SEQ;

    // fused casts (x + 4 weight matrices), one launch
    {
        dim3 g(4096, 5);
        cast_all_kernel<<<g, 256>>>(x, Wq, Wk, Wv, Wo, xh, w);
    }

    // fused qkv projection: [16384 x 3072] = x @ [Wq;Wk;Wv]^T
    {
        dim3 g(3 * DIM / 128, TOK / 128, 1);
        mma_gemm<4><<<g, NTHREADS, SMEMSZ>>>(xh, w, bq, bk, bv,
                                             qh, kh, vth, nullptr,
                                             DIM, DIM, 1.0f, 0, 0, 0);
    }

    // E = exp(SCALE * q @ k^T), fp16, + row partial sums
    {
        dim3 g(SEQ / 128, SEQ / 128, BATCH);
        mma_gemm<5><<<g, NTHREADS, SMEMSZ>>>(qh, kh, nullptr, nullptr, nullptr,
                                             eh, nullptr, nullptr, part,
                                             DIM, SEQ, SCALE, sX, sX, sS);
    }

    // ctx' = 32 * (E @ v) / rowsum   (partials reduced in epilogue)
    {
        dim3 g(DIM / 128, SEQ / 128, BATCH);
        mma_gemm<6><<<g, NTHREADS, SMEMSZ>>>(eh, vth, nullptr, nullptr, nullptr,
                                             ch, nullptr, nullptr, part,
                                             SEQ, DIM, 32.0f, sS, sT, sX);
    }

    // out = (ctx' @ Wo^T)/32 + bo
    {
        dim3 g(DIM / 128, TOK / 128, 1);
        mma_gemm<0><<<g, NTHREADS, SMEMSZ>>>(ch, w + 3ll * DIM * DIM, bo, nullptr, nullptr,
                                             out, nullptr, nullptr, nullptr,
                                             DIM, DIM, 0.03125f, 0, 0, 0);
    }
}

// round 13
// speedup vs baseline: 1.5837x; 1.5837x over previous
#include <cuda_runtime.h>
#include <cuda_fp16.h>
#include <math.h>
#include <stdint.h>

// ---------------------------------------------------------------------------
// SingleHeadAttentionInference B=4, S=4096, D=1024 fp32.
// fp16 mma.sync GEMMs (fp32 acc), 128x128x32 block tile, 4 warps x (64x64)
// + register double-buffered ldmatrix fragments (R11 pipeline).
// Rationale: R11 was smem-crossbar bound at 256B/MMA; 64x64 warp tiles cut
// ldsm traffic to 128B/MMA (192B total) -> crossbar no longer binding.
// Softmax fused into scores epilogue; PV epilogue reduces partials+normalizes.
// ---------------------------------------------------------------------------

#define BATCH 4
#define SEQ   4096
#define DIM   1024
#define TOK   (BATCH*SEQ)
#define SCALE 0.03125f

// ---- scratch ----
__device__ __half g_x  [(size_t)TOK*DIM];
__device__ __half g_q  [(size_t)TOK*DIM];
__device__ __half g_k  [(size_t)TOK*DIM];
__device__ __half g_vt [(size_t)TOK*DIM];             // v^T per batch [b][d][s]
__device__ __half g_c  [(size_t)TOK*DIM];             // 32*ctx
__device__ __half g_e  [(size_t)BATCH*SEQ*SEQ];       // exp(scores), unnormalized
__device__ __half g_w  [4][DIM*DIM];                  // Wq,Wk,Wv,Wo
__device__ float  g_part[(size_t)TOK*32];             // per-(row, nblock) exp sums

// ---------------------------------------------------------------------------
// helpers
// ---------------------------------------------------------------------------
__device__ __forceinline__ uint32_t s2u(const void* p) {
    uint32_t a;
    asm("{ .reg .u64 t; cvta.to.shared.u64 t, %1; cvt.u32.u64 %0, t; }"
        : "=r"(a) : "l"(p));
    return a;
}
__device__ __forceinline__ void cp16(uint32_t s, const void* g) {
    asm volatile("cp.async.cg.shared.global [%0], [%1], 16;" :: "r"(s), "l"(g));
}
__device__ __forceinline__ void ldsm4(uint32_t& r0, uint32_t& r1,
                                      uint32_t& r2, uint32_t& r3, uint32_t a) {
    asm volatile("ldmatrix.sync.aligned.m8n8.x4.shared.b16 {%0,%1,%2,%3}, [%4];"
                 : "=r"(r0), "=r"(r1), "=r"(r2), "=r"(r3) : "r"(a));
}
__device__ __forceinline__ void mma_f16(float* c, const uint32_t* a, const uint32_t* b) {
    asm volatile(
        "mma.sync.aligned.m16n8k16.row.col.f32.f16.f16.f32 "
        "{%0,%1,%2,%3}, {%4,%5,%6,%7}, {%8,%9}, {%0,%1,%2,%3};"
        : "+f"(c[0]), "+f"(c[1]), "+f"(c[2]), "+f"(c[3])
        : "r"(a[0]), "r"(a[1]), "r"(a[2]), "r"(a[3]), "r"(b[0]), "r"(b[1]));
}
__device__ __forceinline__ __half2 h2(float a, float b) {
    __half2 u; u.x = __float2half_rn(a); u.y = __float2half_rn(b); return u;
}

// tile geometry: 128x128 block, BK=32, 80B pitch (conflict-free ldmatrix)
#define ROWP    80
#define TILE_B  (128*ROWP)
#define STAGE_B (2*TILE_B)
#define STAGES  4
#define SMEMSZ  (STAGES*STAGE_B)  // 81920
#define NTHREADS 128

#define STAGE_LOAD(stg_, kc_) do {                                            \
    const size_t k0_ = (size_t)(kc_) << 5;                                    \
    _Pragma("unroll")                                                         \
    for (int j_ = 0; j_ < 8; j_++) {                                          \
        int id_  = tid + j_ * NTHREADS;      /* 0..1023 */                    \
        int t_   = id_ >> 9;                                                  \
        int id2_ = id_ & 511;                                                 \
        int row_ = id2_ >> 2;                                                 \
        int ch_  = id2_ & 3;                                                  \
        uint32_t sa_ = sb + (uint32_t)(stg_) * STAGE_B + (uint32_t)t_ * TILE_B\
                     + (uint32_t)row_ * ROWP + (uint32_t)ch_ * 16;            \
        const __half* src_ = (t_ == 0) ? A : B;                               \
        size_t gr_ = (t_ == 0) ? (bm + row_) : (bn + row_);                   \
        cp16(sa_, src_ + gr_ * (size_t)K + k0_ + ch_ * 8);                    \
    }                                                                         \
    asm volatile("cp.async.commit_group;" ::: "memory");                      \
} while (0)

// load one kk-half's fragments (A: 4 mt, B: 8 nt) into frag buffer fb
#define FRAG_LOAD(fb_, stbase_, kkoff_) do {                                  \
    _Pragma("unroll")                                                         \
    for (int mt_ = 0; mt_ < 4; ++mt_) {                                       \
        uint32_t ba_ = (stbase_) + aOff + (uint32_t)mt_ * (16 * ROWP) + (kkoff_);\
        ldsm4(aF[fb_][mt_][0], aF[fb_][mt_][1], aF[fb_][mt_][2], aF[fb_][mt_][3], ba_);\
    }                                                                         \
    _Pragma("unroll")                                                         \
    for (int ng_ = 0; ng_ < 4; ++ng_) {                                       \
        uint32_t bb_ = (stbase_) + TILE_B + bOff + (uint32_t)ng_ * (16 * ROWP) + (kkoff_);\
        uint32_t r0_, r1_, r2_, r3_;                                          \
        ldsm4(r0_, r1_, r2_, r3_, bb_);                                       \
        bF[fb_][2*ng_][0] = r0_;  bF[fb_][2*ng_+1][0] = r1_;                  \
        bF[fb_][2*ng_][1] = r2_;  bF[fb_][2*ng_+1][1] = r3_;                  \
    }                                                                         \
} while (0)

#define MMA32(fb_) do {                                                       \
    _Pragma("unroll")                                                         \
    for (int mt_ = 0; mt_ < 4; ++mt_)                                         \
        _Pragma("unroll")                                                     \
        for (int nt_ = 0; nt_ < 8; ++nt_)                                     \
            mma_f16(acc[mt_][nt_], aF[fb_][mt_], bF[fb_][nt_]);               \
} while (0)

// ---------------------------------------------------------------------------
// GEMM modes:
//   0 = fp32 out + bias p0
//   4 = fused qkv: cols<1024->q, <2048->k, else v^T; biases p0/p1/p2
//   5 = E-scores: exp(alpha*acc) fp16 + row partial sums -> part
//   6 = ctx: acc * alpha / rowsum(part) -> fp16   (reduces part in-kernel)
// ---------------------------------------------------------------------------
template<int OUT>
__global__ __launch_bounds__(NTHREADS, 2)
void mma_gemm(const __half* __restrict__ A, const __half* __restrict__ B,
              const float* __restrict__ p0, const float* __restrict__ p1,
              const float* __restrict__ p2,
              void* __restrict__ O0, void* __restrict__ O1, void* __restrict__ O2,
              float* __restrict__ part,
              int K, int ldC, float alpha,
              long long sA, long long sB, long long sC)
{
    extern __shared__ char smem[];
    const uint32_t sb = s2u(smem);
    const int tid  = threadIdx.x;
    const int lane = tid & 31;
    const int wid  = tid >> 5;             // 0..3
    const int bz   = blockIdx.z;
    const size_t bm = (size_t)blockIdx.y * 128;
    const size_t bn = (size_t)blockIdx.x * 128;

    A += (size_t)bz * sA;  B += (size_t)bz * sB;

    const int wm = (wid & 1) * 64;         // warp M origin (64-row tile)
    const int wn = (wid >> 1) * 64;        // warp N origin (64-col tile)

    const int lrow = (lane & 7) + ((lane >> 3) & 1) * 8;
    const uint32_t lkc = (uint32_t)((lane >> 4) & 1) * 16;
    const uint32_t aOff = (uint32_t)(wm + lrow) * ROWP + lkc;
    const uint32_t bOff = (uint32_t)(wn + lrow) * ROWP + lkc;

    float acc[4][8][4];
#pragma unroll
    for (int i = 0; i < 4; i++)
#pragma unroll
        for (int j = 0; j < 8; j++)
#pragma unroll
            for (int r = 0; r < 4; r++) acc[i][j][r] = 0.0f;

    const int nk = K >> 5;

    // prologue: 3 stages in flight; stages 0,1 certified
    STAGE_LOAD(0, 0);
    STAGE_LOAD(1, 1);
    STAGE_LOAD(2, 2);
    asm volatile("cp.async.wait_group 1;" ::: "memory");
    __syncthreads();

    uint32_t aF[2][4][4], bF[2][8][2];
    FRAG_LOAD(0, sb, 0u);                          // stage0 kk0

    for (int kc = 0; kc < nk; ++kc) {
        const int nxt = kc + 3;
        if (nxt < nk) STAGE_LOAD(nxt & 3, nxt);
        else asm volatile("cp.async.commit_group;" ::: "memory");

        const uint32_t stc = sb + (uint32_t)(kc & 3) * STAGE_B;
        const uint32_t stn = sb + (uint32_t)((kc + 1) & 3) * STAGE_B;

        FRAG_LOAD(1, stc, 32u);      // kc kk1
        MMA32(0);                    // kc kk0
        if (kc + 1 < nk) FRAG_LOAD(0, stn, 0u);    // kc+1 kk0
        MMA32(1);                    // kc kk1

        asm volatile("cp.async.wait_group 1;" ::: "memory"); // stage kc+2 ready
        __syncthreads();                                     // protect overwrite
    }

    // ---- epilogue ----
    const int gid = lane >> 2, tig = lane & 3;

    if (OUT == 0) {
#pragma unroll
        for (int mt = 0; mt < 4; ++mt) {
            const size_t r0 = bm + wm + mt * 16 + gid;
#pragma unroll
            for (int nt = 0; nt < 8; ++nt) {
                const size_t c = bn + wn + nt * 8 + tig * 2;
                float b0 = p0[c], b1 = p0[c + 1];
                float* o = (float*)O0 + (size_t)bz * sC;
                float2 u0; u0.x = acc[mt][nt][0] * alpha + b0;
                           u0.y = acc[mt][nt][1] * alpha + b1;
                float2 u1; u1.x = acc[mt][nt][2] * alpha + b0;
                           u1.y = acc[mt][nt][3] * alpha + b1;
                *(float2*)(o + r0 * (size_t)ldC + c)       = u0;
                *(float2*)(o + (r0 + 8) * (size_t)ldC + c) = u1;
            }
        }
    } else if (OUT == 4) {
        const int sel = (int)(bn >> 10);           // 0=q,1=k,2=v
        const int cb  = (int)(bn & 1023);
        const float* bias = (sel == 0) ? p0 : (sel == 1) ? p1 : p2;
#pragma unroll
        for (int mt = 0; mt < 4; ++mt) {
            const size_t r0 = bm + wm + mt * 16 + gid;
#pragma unroll
            for (int nt = 0; nt < 8; ++nt) {
                const int lc = cb + wn + nt * 8 + tig * 2;
                float b0 = bias[lc], b1 = bias[lc + 1];
                float v00 = acc[mt][nt][0] + b0, v01 = acc[mt][nt][1] + b1;
                float v10 = acc[mt][nt][2] + b0, v11 = acc[mt][nt][3] + b1;
                if (sel < 2) {
                    __half* o = (sel == 0) ? (__half*)O0 : (__half*)O1;
                    *(__half2*)(o + r0 * (size_t)DIM + lc)       = h2(v00, v01);
                    *(__half2*)(o + (r0 + 8) * (size_t)DIM + lc) = h2(v10, v11);
                } else {
                    const int b = (int)(r0 >> 12);
                    const int s0 = (int)(r0 & 4095);
                    __half* o = (__half*)O2 + (size_t)b * DIM * SEQ;
                    o[(size_t)lc * SEQ + s0]           = __float2half_rn(v00);
                    o[(size_t)(lc + 1) * SEQ + s0]     = __float2half_rn(v01);
                    o[(size_t)lc * SEQ + s0 + 8]       = __float2half_rn(v10);
                    o[(size_t)(lc + 1) * SEQ + s0 + 8] = __float2half_rn(v11);
                }
            }
        }
    } else if (OUT == 5) {
        float ps[4][2];
#pragma unroll
        for (int mt = 0; mt < 4; ++mt) { ps[mt][0] = 0.f; ps[mt][1] = 0.f; }
#pragma unroll
        for (int mt = 0; mt < 4; ++mt) {
            const size_t r0 = bm + wm + mt * 16 + gid;
#pragma unroll
            for (int nt = 0; nt < 8; ++nt) {
                const size_t c = bn + wn + nt * 8 + tig * 2;
                float e00 = __expf(fminf(acc[mt][nt][0] * alpha, 11.0f));
                float e01 = __expf(fminf(acc[mt][nt][1] * alpha, 11.0f));
                float e10 = __expf(fminf(acc[mt][nt][2] * alpha, 11.0f));
                float e11 = __expf(fminf(acc[mt][nt][3] * alpha, 11.0f));
                __half* o = (__half*)O0 + (size_t)bz * sC;
                *(__half2*)(o + r0 * (size_t)ldC + c)       = h2(e00, e01);
                *(__half2*)(o + (r0 + 8) * (size_t)ldC + c) = h2(e10, e11);
                ps[mt][0] += e00 + e01;
                ps[mt][1] += e10 + e11;
            }
        }
#pragma unroll
        for (int mt = 0; mt < 4; ++mt)
#pragma unroll
            for (int sr = 0; sr < 2; ++sr) {
                float v = ps[mt][sr];
                v += __shfl_xor_sync(0xffffffffu, v, 1);
                v += __shfl_xor_sync(0xffffffffu, v, 2);
                ps[mt][sr] = v;
            }
        __syncthreads();
        float* buf = (float*)smem;             // [128 rows][2 n-halves]
        const int half = wid >> 1;             // which 64-col half
        if (tig == 0) {
#pragma unroll
            for (int mt = 0; mt < 4; ++mt) {
                buf[(wm + mt * 16 + gid) * 2 + half]     = ps[mt][0];
                buf[(wm + mt * 16 + gid + 8) * 2 + half] = ps[mt][1];
            }
        }
        __syncthreads();
        {
            float t = buf[tid * 2] + buf[tid * 2 + 1];
            part[((size_t)bz * SEQ + bm + tid) * 32 + blockIdx.x] = t;
        }
    } else {  // OUT == 6: reduce part -> inv in smem, then normalize
        __syncthreads();                       // mainloop smem free
        float* invb = (float*)smem;            // [128]
        {
            const float* pp = part + ((size_t)bz * SEQ + bm + tid) * 32;
            float s = 0.0f;
#pragma unroll
            for (int j = 0; j < 32; j++) s += pp[j];
            invb[tid] = 1.0f / s;
        }
        __syncthreads();
#pragma unroll
        for (int mt = 0; mt < 4; ++mt) {
            const int lr0 = wm + mt * 16 + gid;
            const size_t r0 = bm + lr0;
            const float i0 = invb[lr0]     * alpha;
            const float i1 = invb[lr0 + 8] * alpha;
#pragma unroll
            for (int nt = 0; nt < 8; ++nt) {
                const size_t c = bn + wn + nt * 8 + tig * 2;
                __half* o = (__half*)O0 + (size_t)bz * sC;
                *(__half2*)(o + r0 * (size_t)ldC + c) =
                    h2(acc[mt][nt][0] * i0, acc[mt][nt][1] * i0);
                *(__half2*)(o + (r0 + 8) * (size_t)ldC + c) =
                    h2(acc[mt][nt][2] * i1, acc[mt][nt][3] * i1);
            }
        }
    }
}

// ---------------------------------------------------------------------------
// fused casts: y=0 -> x, y>0 -> weights
// ---------------------------------------------------------------------------
__global__ void cast_all_kernel(const float* __restrict__ x,
                                const float* __restrict__ w0, const float* __restrict__ w1,
                                const float* __restrict__ w2, const float* __restrict__ w3,
                                __half* __restrict__ xh, __half* __restrict__ wh)
{
    const int y = blockIdx.y;
    const float* s;
    __half* d;
    int n4;
    if (y == 0) { s = x;  d = xh; n4 = TOK * DIM / 4; }
    else {
        s = (y == 1) ? w0 : (y == 2) ? w1 : (y == 3) ? w2 : w3;
        d = wh + (size_t)(y - 1) * DIM * DIM;
        n4 = DIM * DIM / 4;
    }
    for (int i = blockIdx.x * blockDim.x + threadIdx.x; i < n4;
         i += gridDim.x * blockDim.x) {
        float4 v = ((const float4*)s)[i];
        ((__half2*)d)[i*2+0] = h2(v.x, v.y);
        ((__half2*)d)[i*2+1] = h2(v.z, v.w);
    }
}

// ---------------------------------------------------------------------------
// launch
// ---------------------------------------------------------------------------
extern "C" void kernel_launch(void* const* d_in, const int* in_sizes, int n_in,
                              void* d_out, int out_size)
{
    const float* x  = (const float*)d_in[0];
    const float* Wq = (const float*)d_in[1];
    const float* bq = (const float*)d_in[2];
    const float* Wk = (const float*)d_in[3];
    const float* bk = (const float*)d_in[4];
    const float* Wv = (const float*)d_in[5];
    const float* bv = (const float*)d_in[6];
    const float* Wo = (const float*)d_in[7];
    const float* bo = (const float*)d_in[8];
    float* out = (float*)d_out;

    __half *xh, *qh, *kh, *vth, *ch, *eh, *w;
    float *part;
    cudaGetSymbolAddress((void**)&xh,   g_x);
    cudaGetSymbolAddress((void**)&qh,   g_q);
    cudaGetSymbolAddress((void**)&kh,   g_k);
    cudaGetSymbolAddress((void**)&vth,  g_vt);
    cudaGetSymbolAddress((void**)&ch,   g_c);
    cudaGetSymbolAddress((void**)&eh,   g_e);
    cudaGetSymbolAddress((void**)&w,    g_w);
    cudaGetSymbolAddress((void**)&part, g_part);

    cudaFuncSetAttribute(mma_gemm<0>, cudaFuncAttributeMaxDynamicSharedMemorySize, SMEMSZ);
    cudaFuncSetAttribute(mma_gemm<4>, cudaFuncAttributeMaxDynamicSharedMemorySize, SMEMSZ);
    cudaFuncSetAttribute(mma_gemm<5>, cudaFuncAttributeMaxDynamicSharedMemorySize, SMEMSZ);
    cudaFuncSetAttribute(mma_gemm<6>, cudaFuncAttributeMaxDynamicSharedMemorySize, SMEMSZ);

    const long long sX = (long long)SEQ * DIM;
    const long long sT = (long long)DIM * SEQ;
    const long long sS = (long long)SEQ * SEQ;

    // fused casts (x + 4 weight matrices), one launch
    {
        dim3 g(4096, 5);
        cast_all_kernel<<<g, 256>>>(x, Wq, Wk, Wv, Wo, xh, w);
    }

    // fused qkv projection: [16384 x 3072] = x @ [Wq;Wk;Wv]^T
    {
        dim3 g(3 * DIM / 128, TOK / 128, 1);
        mma_gemm<4><<<g, NTHREADS, SMEMSZ>>>(xh, w, bq, bk, bv,
                                             qh, kh, vth, nullptr,
                                             DIM, DIM, 1.0f, 0, 0, 0);
    }

    // E = exp(SCALE * q @ k^T), fp16, + row partial sums
    {
        dim3 g(SEQ / 128, SEQ / 128, BATCH);
        mma_gemm<5><<<g, NTHREADS, SMEMSZ>>>(qh, kh, nullptr, nullptr, nullptr,
                                             eh, nullptr, nullptr, part,
                                             DIM, SEQ, SCALE, sX, sX, sS);
    }

    // ctx' = 32 * (E @ v) / rowsum   (partials reduced in epilogue)
    {
        dim3 g(DIM / 128, SEQ / 128, BATCH);
        mma_gemm<6><<<g, NTHREADS, SMEMSZ>>>(eh, vth, nullptr, nullptr, nullptr,
                                             ch, nullptr, nullptr, part,
                                             SEQ, DIM, 32.0f, sS, sT, sX);
    }

    // out = (ctx' @ Wo^T)/32 + bo
    {
        dim3 g(DIM / 128, TOK / 128, 1);
        mma_gemm<0><<<g, NTHREADS, SMEMSZ>>>(ch, w + 3ll * DIM * DIM, bo, nullptr, nullptr,
                                             out, nullptr, nullptr, nullptr,
                                             DIM, DIM, 0.03125f, 0, 0, 0);
    }
}

// round 14
// speedup vs baseline: 1.7400x; 1.0987x over previous
#include <cuda_runtime.h>
#include <cuda_fp16.h>
#include <math.h>
#include <stdint.h>

// ---------------------------------------------------------------------------
// SingleHeadAttentionInference B=4, S=4096, D=1024 fp32.
// fp16 mma.sync (fp32 acc), 128x128 block tile, 4 warps x (64x64),
// register double-buffered fragments (R11/R13 pipeline), NOW with BK=64
// chunks + XOR-swizzled 128B smem rows: ONE wait/__syncthreads per 128 MMAs
// (R13: per 64). 3-stage pipeline, 96KB smem, 2 CTAs/SM.
// Softmax fused into scores epilogue; PV epilogue reduces partials+normalizes.
// ---------------------------------------------------------------------------

#define BATCH 4
#define SEQ   4096
#define DIM   1024
#define TOK   (BATCH*SEQ)
#define SCALE 0.03125f

// ---- scratch ----
__device__ __half g_x  [(size_t)TOK*DIM];
__device__ __half g_q  [(size_t)TOK*DIM];
__device__ __half g_k  [(size_t)TOK*DIM];
__device__ __half g_vt [(size_t)TOK*DIM];             // v^T per batch [b][d][s]
__device__ __half g_c  [(size_t)TOK*DIM];             // 32*ctx
__device__ __half g_e  [(size_t)BATCH*SEQ*SEQ];       // exp(scores), unnormalized
__device__ __half g_w  [4][DIM*DIM];                  // Wq,Wk,Wv,Wo
__device__ float  g_part[(size_t)TOK*32];             // per-(row, nblock) exp sums

// ---------------------------------------------------------------------------
// helpers
// ---------------------------------------------------------------------------
__device__ __forceinline__ uint32_t s2u(const void* p) {
    uint32_t a;
    asm("{ .reg .u64 t; cvta.to.shared.u64 t, %1; cvt.u32.u64 %0, t; }"
        : "=r"(a) : "l"(p));
    return a;
}
__device__ __forceinline__ void cp16(uint32_t s, const void* g) {
    asm volatile("cp.async.cg.shared.global [%0], [%1], 16;" :: "r"(s), "l"(g));
}
__device__ __forceinline__ void ldsm4(uint32_t& r0, uint32_t& r1,
                                      uint32_t& r2, uint32_t& r3, uint32_t a) {
    asm volatile("ldmatrix.sync.aligned.m8n8.x4.shared.b16 {%0,%1,%2,%3}, [%4];"
                 : "=r"(r0), "=r"(r1), "=r"(r2), "=r"(r3) : "r"(a));
}
__device__ __forceinline__ void mma_f16(float* c, const uint32_t* a, const uint32_t* b) {
    asm volatile(
        "mma.sync.aligned.m16n8k16.row.col.f32.f16.f16.f32 "
        "{%0,%1,%2,%3}, {%4,%5,%6,%7}, {%8,%9}, {%0,%1,%2,%3};"
        : "+f"(c[0]), "+f"(c[1]), "+f"(c[2]), "+f"(c[3])
        : "r"(a[0]), "r"(a[1]), "r"(a[2]), "r"(a[3]), "r"(b[0]), "r"(b[1]));
}
__device__ __forceinline__ __half2 h2(float a, float b) {
    __half2 u; u.x = __float2half_rn(a); u.y = __float2half_rn(b); return u;
}

// tile geometry: 128x128 block tile, BK=64 (128B rows, XOR swizzle)
#define TILE_B  (128*128)          // 16384 B per operand tile
#define STAGE_B (2*TILE_B)         // 32768: A, B
#define STAGES  3
#define SMEMSZ  (STAGES*STAGE_B)   // 98304
#define NTHREADS 128

// one stage: 2 tiles x 128 rows x 8 chunks(16B); swizzle c -> c^(row&7)
#define STAGE_LOAD(stg_, kc_) do {                                            \
    const size_t k0_ = (size_t)(kc_) << 6;                                    \
    _Pragma("unroll")                                                         \
    for (int j_ = 0; j_ < 16; j_++) {                                         \
        int id_  = tid + j_ * NTHREADS;      /* 0..2047 */                    \
        int t_   = id_ >> 10;                                                 \
        int id2_ = id_ & 1023;                                                \
        int row_ = id2_ >> 3;                                                 \
        int ch_  = id2_ & 7;                                                  \
        uint32_t sw_ = (uint32_t)(ch_ ^ (row_ & 7));                          \
        uint32_t sa_ = sb + (uint32_t)(stg_) * STAGE_B + (uint32_t)t_ * TILE_B\
                     + (uint32_t)row_ * 128 + sw_ * 16;                       \
        const __half* src_ = (t_ == 0) ? A : B;                               \
        size_t gr_ = (t_ == 0) ? (bm + row_) : (bn + row_);                   \
        cp16(sa_, src_ + gr_ * (size_t)K + k0_ + ch_ * 8);                    \
    }                                                                         \
    asm volatile("cp.async.commit_group;" ::: "memory");                      \
} while (0)

// load fragments for one k16 step kkc (0..3) into frag buffer fb
#define FRAG_LOAD(fb_, stbase_, kkc_) do {                                    \
    const uint32_t co_ = ((uint32_t)(((kkc_) << 1) + hiL) ^ rxL) << 4;        \
    _Pragma("unroll")                                                         \
    for (int mt_ = 0; mt_ < 4; ++mt_) {                                       \
        uint32_t ba_ = (stbase_) + aRow + (uint32_t)mt_ * 2048 + co_;         \
        ldsm4(aF[fb_][mt_][0], aF[fb_][mt_][1], aF[fb_][mt_][2], aF[fb_][mt_][3], ba_);\
    }                                                                         \
    _Pragma("unroll")                                                         \
    for (int ng_ = 0; ng_ < 4; ++ng_) {                                       \
        uint32_t bb_ = (stbase_) + TILE_B + bRow + (uint32_t)ng_ * 2048 + co_;\
        uint32_t r0_, r1_, r2_, r3_;                                          \
        ldsm4(r0_, r1_, r2_, r3_, bb_);                                       \
        bF[fb_][2*ng_][0] = r0_;  bF[fb_][2*ng_+1][0] = r1_;                  \
        bF[fb_][2*ng_][1] = r2_;  bF[fb_][2*ng_+1][1] = r3_;                  \
    }                                                                         \
} while (0)

#define MMA32(fb_) do {                                                       \
    _Pragma("unroll")                                                         \
    for (int mt_ = 0; mt_ < 4; ++mt_)                                         \
        _Pragma("unroll")                                                     \
        for (int nt_ = 0; nt_ < 8; ++nt_)                                     \
            mma_f16(acc[mt_][nt_], aF[fb_][mt_], bF[fb_][nt_]);               \
} while (0)

// ---------------------------------------------------------------------------
// GEMM modes:
//   0 = fp32 out + bias p0
//   4 = fused qkv: cols<1024->q, <2048->k, else v^T; biases p0/p1/p2
//   5 = E-scores: exp(alpha*acc) fp16 + row partial sums -> part
//   6 = ctx: acc * alpha / rowsum(part) -> fp16   (reduces part in-kernel)
// ---------------------------------------------------------------------------
template<int OUT>
__global__ __launch_bounds__(NTHREADS, 2)
void mma_gemm(const __half* __restrict__ A, const __half* __restrict__ B,
              const float* __restrict__ p0, const float* __restrict__ p1,
              const float* __restrict__ p2,
              void* __restrict__ O0, void* __restrict__ O1, void* __restrict__ O2,
              float* __restrict__ part,
              int K, int ldC, float alpha,
              long long sA, long long sB, long long sC)
{
    extern __shared__ char smem[];
    const uint32_t sb = s2u(smem);
    const int tid  = threadIdx.x;
    const int lane = tid & 31;
    const int wid  = tid >> 5;             // 0..3
    const int bz   = blockIdx.z;
    const size_t bm = (size_t)blockIdx.y * 128;
    const size_t bn = (size_t)blockIdx.x * 128;

    A += (size_t)bz * sA;  B += (size_t)bz * sB;

    const int wm = (wid & 1) * 64;         // warp M origin
    const int wn = (wid >> 1) * 64;        // warp N origin

    const int lrow = (lane & 7) + ((lane >> 3) & 1) * 8;
    const uint32_t hiL = (uint32_t)((lane >> 4) & 1);
    const uint32_t rxL = (uint32_t)(lrow & 7);
    const uint32_t aRow = (uint32_t)(wm + lrow) * 128;
    const uint32_t bRow = (uint32_t)(wn + lrow) * 128;

    float acc[4][8][4];
#pragma unroll
    for (int i = 0; i < 4; i++)
#pragma unroll
        for (int j = 0; j < 8; j++)
#pragma unroll
            for (int r = 0; r < 4; r++) acc[i][j][r] = 0.0f;

    const int nk = K >> 6;                 // BK=64 chunks (K % 64 == 0 all sites)

    // prologue: stages 0,1 loaded and certified
    STAGE_LOAD(0, 0);
    STAGE_LOAD(1, 1);
    asm volatile("cp.async.wait_group 0;" ::: "memory");
    __syncthreads();

    uint32_t aF[2][4][4], bF[2][8][2];
    FRAG_LOAD(0, sb, 0);                   // chunk0 kk0

    uint32_t sCur = 0, sNxt = 1, sLd = 2;
    for (int kc = 0; kc < nk; ++kc) {
        if (kc + 2 < nk) STAGE_LOAD(sLd, kc + 2);

        const uint32_t stc = sb + sCur * STAGE_B;
        const uint32_t stn = sb + sNxt * STAGE_B;

        FRAG_LOAD(1, stc, 1);  MMA32(0);   // kk0
        FRAG_LOAD(0, stc, 2);  MMA32(1);   // kk1
        FRAG_LOAD(1, stc, 3);  MMA32(0);   // kk2
        if (kc + 1 < nk) FRAG_LOAD(0, stn, 0);   // next chunk kk0 (certified)
        MMA32(1);                          // kk3

        asm volatile("cp.async.wait_group 0;" ::: "memory");
        __syncthreads();

        uint32_t t = sCur; sCur = sNxt; sNxt = sLd; sLd = t;
    }

    // ---- epilogue ----
    const int gid = lane >> 2, tig = lane & 3;

    if (OUT == 0) {
#pragma unroll
        for (int mt = 0; mt < 4; ++mt) {
            const size_t r0 = bm + wm + mt * 16 + gid;
#pragma unroll
            for (int nt = 0; nt < 8; ++nt) {
                const size_t c = bn + wn + nt * 8 + tig * 2;
                float b0 = p0[c], b1 = p0[c + 1];
                float* o = (float*)O0 + (size_t)bz * sC;
                float2 u0; u0.x = acc[mt][nt][0] * alpha + b0;
                           u0.y = acc[mt][nt][1] * alpha + b1;
                float2 u1; u1.x = acc[mt][nt][2] * alpha + b0;
                           u1.y = acc[mt][nt][3] * alpha + b1;
                *(float2*)(o + r0 * (size_t)ldC + c)       = u0;
                *(float2*)(o + (r0 + 8) * (size_t)ldC + c) = u1;
            }
        }
    } else if (OUT == 4) {
        const int sel = (int)(bn >> 10);           // 0=q,1=k,2=v
        const int cb  = (int)(bn & 1023);
        const float* bias = (sel == 0) ? p0 : (sel == 1) ? p1 : p2;
#pragma unroll
        for (int mt = 0; mt < 4; ++mt) {
            const size_t r0 = bm + wm + mt * 16 + gid;
#pragma unroll
            for (int nt = 0; nt < 8; ++nt) {
                const int lc = cb + wn + nt * 8 + tig * 2;
                float b0 = bias[lc], b1 = bias[lc + 1];
                float v00 = acc[mt][nt][0] + b0, v01 = acc[mt][nt][1] + b1;
                float v10 = acc[mt][nt][2] + b0, v11 = acc[mt][nt][3] + b1;
                if (sel < 2) {
                    __half* o = (sel == 0) ? (__half*)O0 : (__half*)O1;
                    *(__half2*)(o + r0 * (size_t)DIM + lc)       = h2(v00, v01);
                    *(__half2*)(o + (r0 + 8) * (size_t)DIM + lc) = h2(v10, v11);
                } else {
                    const int b = (int)(r0 >> 12);
                    const int s0 = (int)(r0 & 4095);
                    __half* o = (__half*)O2 + (size_t)b * DIM * SEQ;
                    o[(size_t)lc * SEQ + s0]           = __float2half_rn(v00);
                    o[(size_t)(lc + 1) * SEQ + s0]     = __float2half_rn(v01);
                    o[(size_t)lc * SEQ + s0 + 8]       = __float2half_rn(v10);
                    o[(size_t)(lc + 1) * SEQ + s0 + 8] = __float2half_rn(v11);
                }
            }
        }
    } else if (OUT == 5) {
        float ps[4][2];
#pragma unroll
        for (int mt = 0; mt < 4; ++mt) { ps[mt][0] = 0.f; ps[mt][1] = 0.f; }
#pragma unroll
        for (int mt = 0; mt < 4; ++mt) {
            const size_t r0 = bm + wm + mt * 16 + gid;
#pragma unroll
            for (int nt = 0; nt < 8; ++nt) {
                const size_t c = bn + wn + nt * 8 + tig * 2;
                float e00 = __expf(fminf(acc[mt][nt][0] * alpha, 11.0f));
                float e01 = __expf(fminf(acc[mt][nt][1] * alpha, 11.0f));
                float e10 = __expf(fminf(acc[mt][nt][2] * alpha, 11.0f));
                float e11 = __expf(fminf(acc[mt][nt][3] * alpha, 11.0f));
                __half* o = (__half*)O0 + (size_t)bz * sC;
                *(__half2*)(o + r0 * (size_t)ldC + c)       = h2(e00, e01);
                *(__half2*)(o + (r0 + 8) * (size_t)ldC + c) = h2(e10, e11);
                ps[mt][0] += e00 + e01;
                ps[mt][1] += e10 + e11;
            }
        }
#pragma unroll
        for (int mt = 0; mt < 4; ++mt)
#pragma unroll
            for (int sr = 0; sr < 2; ++sr) {
                float v = ps[mt][sr];
                v += __shfl_xor_sync(0xffffffffu, v, 1);
                v += __shfl_xor_sync(0xffffffffu, v, 2);
                ps[mt][sr] = v;
            }
        __syncthreads();
        float* buf = (float*)smem;             // [128 rows][2 n-halves]
        const int half = wid >> 1;             // which 64-col half
        if (tig == 0) {
#pragma unroll
            for (int mt = 0; mt < 4; ++mt) {
                buf[(wm + mt * 16 + gid) * 2 + half]     = ps[mt][0];
                buf[(wm + mt * 16 + gid + 8) * 2 + half] = ps[mt][1];
            }
        }
        __syncthreads();
        {
            float t = buf[tid * 2] + buf[tid * 2 + 1];
            part[((size_t)bz * SEQ + bm + tid) * 32 + blockIdx.x] = t;
        }
    } else {  // OUT == 6: reduce part -> inv in smem, then normalize
        __syncthreads();                       // mainloop smem free
        float* invb = (float*)smem;            // [128]
        {
            const float* pp = part + ((size_t)bz * SEQ + bm + tid) * 32;
            float s = 0.0f;
#pragma unroll
            for (int j = 0; j < 32; j++) s += pp[j];
            invb[tid] = 1.0f / s;
        }
        __syncthreads();
#pragma unroll
        for (int mt = 0; mt < 4; ++mt) {
            const int lr0 = wm + mt * 16 + gid;
            const size_t r0 = bm + lr0;
            const float i0 = invb[lr0]     * alpha;
            const float i1 = invb[lr0 + 8] * alpha;
#pragma unroll
            for (int nt = 0; nt < 8; ++nt) {
                const size_t c = bn + wn + nt * 8 + tig * 2;
                __half* o = (__half*)O0 + (size_t)bz * sC;
                *(__half2*)(o + r0 * (size_t)ldC + c) =
                    h2(acc[mt][nt][0] * i0, acc[mt][nt][1] * i0);
                *(__half2*)(o + (r0 + 8) * (size_t)ldC + c) =
                    h2(acc[mt][nt][2] * i1, acc[mt][nt][3] * i1);
            }
        }
    }
}

// ---------------------------------------------------------------------------
// fused casts: y=0 -> x, y>0 -> weights
// ---------------------------------------------------------------------------
__global__ void cast_all_kernel(const float* __restrict__ x,
                                const float* __restrict__ w0, const float* __restrict__ w1,
                                const float* __restrict__ w2, const float* __restrict__ w3,
                                __half* __restrict__ xh, __half* __restrict__ wh)
{
    const int y = blockIdx.y;
    const float* s;
    __half* d;
    int n4;
    if (y == 0) { s = x;  d = xh; n4 = TOK * DIM / 4; }
    else {
        s = (y == 1) ? w0 : (y == 2) ? w1 : (y == 3) ? w2 : w3;
        d = wh + (size_t)(y - 1) * DIM * DIM;
        n4 = DIM * DIM / 4;
    }
    for (int i = blockIdx.x * blockDim.x + threadIdx.x; i < n4;
         i += gridDim.x * blockDim.x) {
        float4 v = ((const float4*)s)[i];
        ((__half2*)d)[i*2+0] = h2(v.x, v.y);
        ((__half2*)d)[i*2+1] = h2(v.z, v.w);
    }
}

// ---------------------------------------------------------------------------
// launch
// ---------------------------------------------------------------------------
extern "C" void kernel_launch(void* const* d_in, const int* in_sizes, int n_in,
                              void* d_out, int out_size)
{
    const float* x  = (const float*)d_in[0];
    const float* Wq = (const float*)d_in[1];
    const float* bq = (const float*)d_in[2];
    const float* Wk = (const float*)d_in[3];
    const float* bk = (const float*)d_in[4];
    const float* Wv = (const float*)d_in[5];
    const float* bv = (const float*)d_in[6];
    const float* Wo = (const float*)d_in[7];
    const float* bo = (const float*)d_in[8];
    float* out = (float*)d_out;

    __half *xh, *qh, *kh, *vth, *ch, *eh, *w;
    float *part;
    cudaGetSymbolAddress((void**)&xh,   g_x);
    cudaGetSymbolAddress((void**)&qh,   g_q);
    cudaGetSymbolAddress((void**)&kh,   g_k);
    cudaGetSymbolAddress((void**)&vth,  g_vt);
    cudaGetSymbolAddress((void**)&ch,   g_c);
    cudaGetSymbolAddress((void**)&eh,   g_e);
    cudaGetSymbolAddress((void**)&w,    g_w);
    cudaGetSymbolAddress((void**)&part, g_part);

    cudaFuncSetAttribute(mma_gemm<0>, cudaFuncAttributeMaxDynamicSharedMemorySize, SMEMSZ);
    cudaFuncSetAttribute(mma_gemm<4>, cudaFuncAttributeMaxDynamicSharedMemorySize, SMEMSZ);
    cudaFuncSetAttribute(mma_gemm<5>, cudaFuncAttributeMaxDynamicSharedMemorySize, SMEMSZ);
    cudaFuncSetAttribute(mma_gemm<6>, cudaFuncAttributeMaxDynamicSharedMemorySize, SMEMSZ);

    const long long sX = (long long)SEQ * DIM;
    const long long sT = (long long)DIM * SEQ;
    const long long sS = (long long)SEQ * SEQ;

    // fused casts (x + 4 weight matrices), one launch
    {
        dim3 g(4096, 5);
        cast_all_kernel<<<g, 256>>>(x, Wq, Wk, Wv, Wo, xh, w);
    }

    // fused qkv projection: [16384 x 3072] = x @ [Wq;Wk;Wv]^T
    {
        dim3 g(3 * DIM / 128, TOK / 128, 1);
        mma_gemm<4><<<g, NTHREADS, SMEMSZ>>>(xh, w, bq, bk, bv,
                                             qh, kh, vth, nullptr,
                                             DIM, DIM, 1.0f, 0, 0, 0);
    }

    // E = exp(SCALE * q @ k^T), fp16, + row partial sums
    {
        dim3 g(SEQ / 128, SEQ / 128, BATCH);
        mma_gemm<5><<<g, NTHREADS, SMEMSZ>>>(qh, kh, nullptr, nullptr, nullptr,
                                             eh, nullptr, nullptr, part,
                                             DIM, SEQ, SCALE, sX, sX, sS);
    }

    // ctx' = 32 * (E @ v) / rowsum   (partials reduced in epilogue)
    {
        dim3 g(DIM / 128, SEQ / 128, BATCH);
        mma_gemm<6><<<g, NTHREADS, SMEMSZ>>>(eh, vth, nullptr, nullptr, nullptr,
                                             ch, nullptr, nullptr, part,
                                             SEQ, DIM, 32.0f, sS, sT, sX);
    }

    // out = (ctx' @ Wo^T)/32 + bo
    {
        dim3 g(DIM / 128, TOK / 128, 1);
        mma_gemm<0><<<g, NTHREADS, SMEMSZ>>>(ch, w + 3ll * DIM * DIM, bo, nullptr, nullptr,
                                             out, nullptr, nullptr, nullptr,
                                             DIM, DIM, 0.03125f, 0, 0, 0);
    }
}

// round 15
// speedup vs baseline: 1.7646x; 1.0141x over previous
#include <cuda_runtime.h>
#include <cuda_fp16.h>
#include <math.h>
#include <stdint.h>

// ---------------------------------------------------------------------------
// SingleHeadAttentionInference B=4, S=4096, D=1024 fp32.
// fp16 mma.sync (fp32 acc), 128x128 block tile, 4 warps x (64x64),
// register double-buffered fragments, BK=64 XOR-swizzled chunks (R14),
// FIXED: wait_group 1 (not 0) so the just-issued stage load stays in flight
// instead of exposing a full memory round trip per chunk.
// Softmax fused into scores epilogue; PV epilogue reduces partials+normalizes.
// ---------------------------------------------------------------------------

#define BATCH 4
#define SEQ   4096
#define DIM   1024
#define TOK   (BATCH*SEQ)
#define SCALE 0.03125f

// ---- scratch ----
__device__ __half g_x  [(size_t)TOK*DIM];
__device__ __half g_q  [(size_t)TOK*DIM];
__device__ __half g_k  [(size_t)TOK*DIM];
__device__ __half g_vt [(size_t)TOK*DIM];             // v^T per batch [b][d][s]
__device__ __half g_c  [(size_t)TOK*DIM];             // 32*ctx
__device__ __half g_e  [(size_t)BATCH*SEQ*SEQ];       // exp(scores), unnormalized
__device__ __half g_w  [4][DIM*DIM];                  // Wq,Wk,Wv,Wo
__device__ float  g_part[(size_t)TOK*32];             // per-(row, nblock) exp sums

// ---------------------------------------------------------------------------
// helpers
// ---------------------------------------------------------------------------
__device__ __forceinline__ uint32_t s2u(const void* p) {
    uint32_t a;
    asm("{ .reg .u64 t; cvta.to.shared.u64 t, %1; cvt.u32.u64 %0, t; }"
        : "=r"(a) : "l"(p));
    return a;
}
__device__ __forceinline__ void cp16(uint32_t s, const void* g) {
    asm volatile("cp.async.cg.shared.global [%0], [%1], 16;" :: "r"(s), "l"(g));
}
__device__ __forceinline__ void ldsm4(uint32_t& r0, uint32_t& r1,
                                      uint32_t& r2, uint32_t& r3, uint32_t a) {
    asm volatile("ldmatrix.sync.aligned.m8n8.x4.shared.b16 {%0,%1,%2,%3}, [%4];"
                 : "=r"(r0), "=r"(r1), "=r"(r2), "=r"(r3) : "r"(a));
}
__device__ __forceinline__ void mma_f16(float* c, const uint32_t* a, const uint32_t* b) {
    asm volatile(
        "mma.sync.aligned.m16n8k16.row.col.f32.f16.f16.f32 "
        "{%0,%1,%2,%3}, {%4,%5,%6,%7}, {%8,%9}, {%0,%1,%2,%3};"
        : "+f"(c[0]), "+f"(c[1]), "+f"(c[2]), "+f"(c[3])
        : "r"(a[0]), "r"(a[1]), "r"(a[2]), "r"(a[3]), "r"(b[0]), "r"(b[1]));
}
__device__ __forceinline__ __half2 h2(float a, float b) {
    __half2 u; u.x = __float2half_rn(a); u.y = __float2half_rn(b); return u;
}

// tile geometry: 128x128 block tile, BK=64 (128B rows, XOR swizzle)
#define TILE_B  (128*128)          // 16384 B per operand tile
#define STAGE_B (2*TILE_B)         // 32768: A, B
#define STAGES  3
#define SMEMSZ  (STAGES*STAGE_B)   // 98304
#define NTHREADS 128

// one stage: 2 tiles x 128 rows x 8 chunks(16B); swizzle c -> c^(row&7)
#define STAGE_LOAD(stg_, kc_) do {                                            \
    const size_t k0_ = (size_t)(kc_) << 6;                                    \
    _Pragma("unroll")                                                         \
    for (int j_ = 0; j_ < 16; j_++) {                                         \
        int id_  = tid + j_ * NTHREADS;      /* 0..2047 */                    \
        int t_   = id_ >> 10;                                                 \
        int id2_ = id_ & 1023;                                                \
        int row_ = id2_ >> 3;                                                 \
        int ch_  = id2_ & 7;                                                  \
        uint32_t sw_ = (uint32_t)(ch_ ^ (row_ & 7));                          \
        uint32_t sa_ = sb + (uint32_t)(stg_) * STAGE_B + (uint32_t)t_ * TILE_B\
                     + (uint32_t)row_ * 128 + sw_ * 16;                       \
        const __half* src_ = (t_ == 0) ? A : B;                               \
        size_t gr_ = (t_ == 0) ? (bm + row_) : (bn + row_);                   \
        cp16(sa_, src_ + gr_ * (size_t)K + k0_ + ch_ * 8);                    \
    }                                                                         \
    asm volatile("cp.async.commit_group;" ::: "memory");                      \
} while (0)

// load fragments for one k16 step kkc (0..3) into frag buffer fb
#define FRAG_LOAD(fb_, stbase_, kkc_) do {                                    \
    const uint32_t co_ = ((uint32_t)(((kkc_) << 1) + hiL) ^ rxL) << 4;        \
    _Pragma("unroll")                                                         \
    for (int mt_ = 0; mt_ < 4; ++mt_) {                                       \
        uint32_t ba_ = (stbase_) + aRow + (uint32_t)mt_ * 2048 + co_;         \
        ldsm4(aF[fb_][mt_][0], aF[fb_][mt_][1], aF[fb_][mt_][2], aF[fb_][mt_][3], ba_);\
    }                                                                         \
    _Pragma("unroll")                                                         \
    for (int ng_ = 0; ng_ < 4; ++ng_) {                                       \
        uint32_t bb_ = (stbase_) + TILE_B + bRow + (uint32_t)ng_ * 2048 + co_;\
        uint32_t r0_, r1_, r2_, r3_;                                          \
        ldsm4(r0_, r1_, r2_, r3_, bb_);                                       \
        bF[fb_][2*ng_][0] = r0_;  bF[fb_][2*ng_+1][0] = r1_;                  \
        bF[fb_][2*ng_][1] = r2_;  bF[fb_][2*ng_+1][1] = r3_;                  \
    }                                                                         \
} while (0)

#define MMA32(fb_) do {                                                       \
    _Pragma("unroll")                                                         \
    for (int mt_ = 0; mt_ < 4; ++mt_)                                         \
        _Pragma("unroll")                                                     \
        for (int nt_ = 0; nt_ < 8; ++nt_)                                     \
            mma_f16(acc[mt_][nt_], aF[fb_][mt_], bF[fb_][nt_]);               \
} while (0)

// ---------------------------------------------------------------------------
// GEMM modes:
//   0 = fp32 out + bias p0
//   4 = fused qkv: cols<1024->q, <2048->k, else v^T; biases p0/p1/p2
//   5 = E-scores: exp(alpha*acc) fp16 + row partial sums -> part
//   6 = ctx: acc * alpha / rowsum(part) -> fp16   (reduces part in-kernel)
// ---------------------------------------------------------------------------
template<int OUT>
__global__ __launch_bounds__(NTHREADS, 2)
void mma_gemm(const __half* __restrict__ A, const __half* __restrict__ B,
              const float* __restrict__ p0, const float* __restrict__ p1,
              const float* __restrict__ p2,
              void* __restrict__ O0, void* __restrict__ O1, void* __restrict__ O2,
              float* __restrict__ part,
              int K, int ldC, float alpha,
              long long sA, long long sB, long long sC)
{
    extern __shared__ char smem[];
    const uint32_t sb = s2u(smem);
    const int tid  = threadIdx.x;
    const int lane = tid & 31;
    const int wid  = tid >> 5;             // 0..3
    const int bz   = blockIdx.z;
    const size_t bm = (size_t)blockIdx.y * 128;
    const size_t bn = (size_t)blockIdx.x * 128;

    A += (size_t)bz * sA;  B += (size_t)bz * sB;

    const int wm = (wid & 1) * 64;         // warp M origin
    const int wn = (wid >> 1) * 64;        // warp N origin

    const int lrow = (lane & 7) + ((lane >> 3) & 1) * 8;
    const uint32_t hiL = (uint32_t)((lane >> 4) & 1);
    const uint32_t rxL = (uint32_t)(lrow & 7);
    const uint32_t aRow = (uint32_t)(wm + lrow) * 128;
    const uint32_t bRow = (uint32_t)(wn + lrow) * 128;

    float acc[4][8][4];
#pragma unroll
    for (int i = 0; i < 4; i++)
#pragma unroll
        for (int j = 0; j < 8; j++)
#pragma unroll
            for (int r = 0; r < 4; r++) acc[i][j][r] = 0.0f;

    const int nk = K >> 6;                 // BK=64 chunks (K % 64 == 0 all sites)

    // prologue: stages 0,1 loaded and certified
    STAGE_LOAD(0, 0);
    STAGE_LOAD(1, 1);
    asm volatile("cp.async.wait_group 0;" ::: "memory");
    __syncthreads();

    uint32_t aF[2][4][4], bF[2][8][2];
    FRAG_LOAD(0, sb, 0);                   // chunk0 kk0

    uint32_t sCur = 0, sNxt = 1, sLd = 2;
    for (int kc = 0; kc < nk; ++kc) {
        if (kc + 2 < nk) STAGE_LOAD(sLd, kc + 2);
        else asm volatile("cp.async.commit_group;" ::: "memory");

        const uint32_t stc = sb + sCur * STAGE_B;
        const uint32_t stn = sb + sNxt * STAGE_B;

        FRAG_LOAD(1, stc, 1);  MMA32(0);   // kk0
        FRAG_LOAD(0, stc, 2);  MMA32(1);   // kk1
        FRAG_LOAD(1, stc, 3);  MMA32(0);   // kk2
        MMA32(1);                          // kk3

        // certify stage kc+1 (group kc+2 may stay in flight)
        asm volatile("cp.async.wait_group 1;" ::: "memory");
        __syncthreads();

        if (kc + 1 < nk) FRAG_LOAD(0, stn, 0);   // next chunk kk0 (certified)

        uint32_t t = sCur; sCur = sNxt; sNxt = sLd; sLd = t;
    }

    // ---- epilogue ----
    const int gid = lane >> 2, tig = lane & 3;

    if (OUT == 0) {
#pragma unroll
        for (int mt = 0; mt < 4; ++mt) {
            const size_t r0 = bm + wm + mt * 16 + gid;
#pragma unroll
            for (int nt = 0; nt < 8; ++nt) {
                const size_t c = bn + wn + nt * 8 + tig * 2;
                float b0 = p0[c], b1 = p0[c + 1];
                float* o = (float*)O0 + (size_t)bz * sC;
                float2 u0; u0.x = acc[mt][nt][0] * alpha + b0;
                           u0.y = acc[mt][nt][1] * alpha + b1;
                float2 u1; u1.x = acc[mt][nt][2] * alpha + b0;
                           u1.y = acc[mt][nt][3] * alpha + b1;
                *(float2*)(o + r0 * (size_t)ldC + c)       = u0;
                *(float2*)(o + (r0 + 8) * (size_t)ldC + c) = u1;
            }
        }
    } else if (OUT == 4) {
        const int sel = (int)(bn >> 10);           // 0=q,1=k,2=v
        const int cb  = (int)(bn & 1023);
        const float* bias = (sel == 0) ? p0 : (sel == 1) ? p1 : p2;
#pragma unroll
        for (int mt = 0; mt < 4; ++mt) {
            const size_t r0 = bm + wm + mt * 16 + gid;
#pragma unroll
            for (int nt = 0; nt < 8; ++nt) {
                const int lc = cb + wn + nt * 8 + tig * 2;
                float b0 = bias[lc], b1 = bias[lc + 1];
                float v00 = acc[mt][nt][0] + b0, v01 = acc[mt][nt][1] + b1;
                float v10 = acc[mt][nt][2] + b0, v11 = acc[mt][nt][3] + b1;
                if (sel < 2) {
                    __half* o = (sel == 0) ? (__half*)O0 : (__half*)O1;
                    *(__half2*)(o + r0 * (size_t)DIM + lc)       = h2(v00, v01);
                    *(__half2*)(o + (r0 + 8) * (size_t)DIM + lc) = h2(v10, v11);
                } else {
                    const int b = (int)(r0 >> 12);
                    const int s0 = (int)(r0 & 4095);
                    __half* o = (__half*)O2 + (size_t)b * DIM * SEQ;
                    o[(size_t)lc * SEQ + s0]           = __float2half_rn(v00);
                    o[(size_t)(lc + 1) * SEQ + s0]     = __float2half_rn(v01);
                    o[(size_t)lc * SEQ + s0 + 8]       = __float2half_rn(v10);
                    o[(size_t)(lc + 1) * SEQ + s0 + 8] = __float2half_rn(v11);
                }
            }
        }
    } else if (OUT == 5) {
        float ps[4][2];
#pragma unroll
        for (int mt = 0; mt < 4; ++mt) { ps[mt][0] = 0.f; ps[mt][1] = 0.f; }
#pragma unroll
        for (int mt = 0; mt < 4; ++mt) {
            const size_t r0 = bm + wm + mt * 16 + gid;
#pragma unroll
            for (int nt = 0; nt < 8; ++nt) {
                const size_t c = bn + wn + nt * 8 + tig * 2;
                float e00 = __expf(fminf(acc[mt][nt][0] * alpha, 11.0f));
                float e01 = __expf(fminf(acc[mt][nt][1] * alpha, 11.0f));
                float e10 = __expf(fminf(acc[mt][nt][2] * alpha, 11.0f));
                float e11 = __expf(fminf(acc[mt][nt][3] * alpha, 11.0f));
                __half* o = (__half*)O0 + (size_t)bz * sC;
                *(__half2*)(o + r0 * (size_t)ldC + c)       = h2(e00, e01);
                *(__half2*)(o + (r0 + 8) * (size_t)ldC + c) = h2(e10, e11);
                ps[mt][0] += e00 + e01;
                ps[mt][1] += e10 + e11;
            }
        }
#pragma unroll
        for (int mt = 0; mt < 4; ++mt)
#pragma unroll
            for (int sr = 0; sr < 2; ++sr) {
                float v = ps[mt][sr];
                v += __shfl_xor_sync(0xffffffffu, v, 1);
                v += __shfl_xor_sync(0xffffffffu, v, 2);
                ps[mt][sr] = v;
            }
        __syncthreads();
        float* buf = (float*)smem;             // [128 rows][2 n-halves]
        const int half = wid >> 1;             // which 64-col half
        if (tig == 0) {
#pragma unroll
            for (int mt = 0; mt < 4; ++mt) {
                buf[(wm + mt * 16 + gid) * 2 + half]     = ps[mt][0];
                buf[(wm + mt * 16 + gid + 8) * 2 + half] = ps[mt][1];
            }
        }
        __syncthreads();
        {
            float t = buf[tid * 2] + buf[tid * 2 + 1];
            part[((size_t)bz * SEQ + bm + tid) * 32 + blockIdx.x] = t;
        }
    } else {  // OUT == 6: reduce part -> inv in smem, then normalize
        __syncthreads();                       // mainloop smem free
        float* invb = (float*)smem;            // [128]
        {
            const float* pp = part + ((size_t)bz * SEQ + bm + tid) * 32;
            float s = 0.0f;
#pragma unroll
            for (int j = 0; j < 32; j++) s += pp[j];
            invb[tid] = 1.0f / s;
        }
        __syncthreads();
#pragma unroll
        for (int mt = 0; mt < 4; ++mt) {
            const int lr0 = wm + mt * 16 + gid;
            const size_t r0 = bm + lr0;
            const float i0 = invb[lr0]     * alpha;
            const float i1 = invb[lr0 + 8] * alpha;
#pragma unroll
            for (int nt = 0; nt < 8; ++nt) {
                const size_t c = bn + wn + nt * 8 + tig * 2;
                __half* o = (__half*)O0 + (size_t)bz * sC;
                *(__half2*)(o + r0 * (size_t)ldC + c) =
                    h2(acc[mt][nt][0] * i0, acc[mt][nt][1] * i0);
                *(__half2*)(o + (r0 + 8) * (size_t)ldC + c) =
                    h2(acc[mt][nt][2] * i1, acc[mt][nt][3] * i1);
            }
        }
    }
}

// ---------------------------------------------------------------------------
// fused casts: y=0 -> x, y>0 -> weights
// ---------------------------------------------------------------------------
__global__ void cast_all_kernel(const float* __restrict__ x,
                                const float* __restrict__ w0, const float* __restrict__ w1,
                                const float* __restrict__ w2, const float* __restrict__ w3,
                                __half* __restrict__ xh, __half* __restrict__ wh)
{
    const int y = blockIdx.y;
    const float* s;
    __half* d;
    int n4;
    if (y == 0) { s = x;  d = xh; n4 = TOK * DIM / 4; }
    else {
        s = (y == 1) ? w0 : (y == 2) ? w1 : (y == 3) ? w2 : w3;
        d = wh + (size_t)(y - 1) * DIM * DIM;
        n4 = DIM * DIM / 4;
    }
    for (int i = blockIdx.x * blockDim.x + threadIdx.x; i < n4;
         i += gridDim.x * blockDim.x) {
        float4 v = ((const float4*)s)[i];
        ((__half2*)d)[i*2+0] = h2(v.x, v.y);
        ((__half2*)d)[i*2+1] = h2(v.z, v.w);
    }
}

// ---------------------------------------------------------------------------
// launch
// ---------------------------------------------------------------------------
extern "C" void kernel_launch(void* const* d_in, const int* in_sizes, int n_in,
                              void* d_out, int out_size)
{
    const float* x  = (const float*)d_in[0];
    const float* Wq = (const float*)d_in[1];
    const float* bq = (const float*)d_in[2];
    const float* Wk = (const float*)d_in[3];
    const float* bk = (const float*)d_in[4];
    const float* Wv = (const float*)d_in[5];
    const float* bv = (const float*)d_in[6];
    const float* Wo = (const float*)d_in[7];
    const float* bo = (const float*)d_in[8];
    float* out = (float*)d_out;

    __half *xh, *qh, *kh, *vth, *ch, *eh, *w;
    float *part;
    cudaGetSymbolAddress((void**)&xh,   g_x);
    cudaGetSymbolAddress((void**)&qh,   g_q);
    cudaGetSymbolAddress((void**)&kh,   g_k);
    cudaGetSymbolAddress((void**)&vth,  g_vt);
    cudaGetSymbolAddress((void**)&ch,   g_c);
    cudaGetSymbolAddress((void**)&eh,   g_e);
    cudaGetSymbolAddress((void**)&w,    g_w);
    cudaGetSymbolAddress((void**)&part, g_part);

    cudaFuncSetAttribute(mma_gemm<0>, cudaFuncAttributeMaxDynamicSharedMemorySize, SMEMSZ);
    cudaFuncSetAttribute(mma_gemm<4>, cudaFuncAttributeMaxDynamicSharedMemorySize, SMEMSZ);
    cudaFuncSetAttribute(mma_gemm<5>, cudaFuncAttributeMaxDynamicSharedMemorySize, SMEMSZ);
    cudaFuncSetAttribute(mma_gemm<6>, cudaFuncAttributeMaxDynamicSharedMemorySize, SMEMSZ);

    const long long sX = (long long)SEQ * DIM;
    const long long sT = (long long)DIM * SEQ;
    const long long sS = (long long)SEQ * SEQ;

    // fused casts (x + 4 weight matrices), one launch
    {
        dim3 g(4096, 5);
        cast_all_kernel<<<g, 256>>>(x, Wq, Wk, Wv, Wo, xh, w);
    }

    // fused qkv projection: [16384 x 3072] = x @ [Wq;Wk;Wv]^T
    {
        dim3 g(3 * DIM / 128, TOK / 128, 1);
        mma_gemm<4><<<g, NTHREADS, SMEMSZ>>>(xh, w, bq, bk, bv,
                                             qh, kh, vth, nullptr,
                                             DIM, DIM, 1.0f, 0, 0, 0);
    }

    // E = exp(SCALE * q @ k^T), fp16, + row partial sums
    {
        dim3 g(SEQ / 128, SEQ / 128, BATCH);
        mma_gemm<5><<<g, NTHREADS, SMEMSZ>>>(qh, kh, nullptr, nullptr, nullptr,
                                             eh, nullptr, nullptr, part,
                                             DIM, SEQ, SCALE, sX, sX, sS);
    }

    // ctx' = 32 * (E @ v) / rowsum   (partials reduced in epilogue)
    {
        dim3 g(DIM / 128, SEQ / 128, BATCH);
        mma_gemm<6><<<g, NTHREADS, SMEMSZ>>>(eh, vth, nullptr, nullptr, nullptr,
                                             ch, nullptr, nullptr, part,
                                             SEQ, DIM, 32.0f, sS, sT, sX);
    }

    // out = (ctx' @ Wo^T)/32 + bo
    {
        dim3 g(DIM / 128, TOK / 128, 1);
        mma_gemm<0><<<g, NTHREADS, SMEMSZ>>>(ch, w + 3ll * DIM * DIM, bo, nullptr, nullptr,
                                             out, nullptr, nullptr, nullptr,
                                             DIM, DIM, 0.03125f, 0, 0, 0);
    }
}

// round 16
// speedup vs baseline: 1.8867x; 1.0692x over previous
#include <cuda_runtime.h>
#include <cuda_fp16.h>
#include <math.h>
#include <stdint.h>

// ---------------------------------------------------------------------------
// SingleHeadAttentionInference B=4, S=4096, D=1024 fp32.
// fp16 mma.sync (fp32 acc), 128x128 block tile, 4 warps x (64x64),
// register double-buffered fragments, BK=64 XOR-swizzled chunks,
// wait_group 1 pipeline (R15) + NEW: stage-load cp.asyncs interleaved into
// the MMA stream in quarters to remove the chunk-top LSU burst.
// Softmax fused into scores epilogue; PV epilogue reduces partials+normalizes.
// ---------------------------------------------------------------------------

#define BATCH 4
#define SEQ   4096
#define DIM   1024
#define TOK   (BATCH*SEQ)
#define SCALE 0.03125f

// ---- scratch ----
__device__ __half g_x  [(size_t)TOK*DIM];
__device__ __half g_q  [(size_t)TOK*DIM];
__device__ __half g_k  [(size_t)TOK*DIM];
__device__ __half g_vt [(size_t)TOK*DIM];             // v^T per batch [b][d][s]
__device__ __half g_c  [(size_t)TOK*DIM];             // 32*ctx
__device__ __half g_e  [(size_t)BATCH*SEQ*SEQ];       // exp(scores), unnormalized
__device__ __half g_w  [4][DIM*DIM];                  // Wq,Wk,Wv,Wo
__device__ float  g_part[(size_t)TOK*32];             // per-(row, nblock) exp sums

// ---------------------------------------------------------------------------
// helpers
// ---------------------------------------------------------------------------
__device__ __forceinline__ uint32_t s2u(const void* p) {
    uint32_t a;
    asm("{ .reg .u64 t; cvta.to.shared.u64 t, %1; cvt.u32.u64 %0, t; }"
        : "=r"(a) : "l"(p));
    return a;
}
__device__ __forceinline__ void cp16(uint32_t s, const void* g) {
    asm volatile("cp.async.cg.shared.global [%0], [%1], 16;" :: "r"(s), "l"(g));
}
__device__ __forceinline__ void ldsm4(uint32_t& r0, uint32_t& r1,
                                      uint32_t& r2, uint32_t& r3, uint32_t a) {
    asm volatile("ldmatrix.sync.aligned.m8n8.x4.shared.b16 {%0,%1,%2,%3}, [%4];"
                 : "=r"(r0), "=r"(r1), "=r"(r2), "=r"(r3) : "r"(a));
}
__device__ __forceinline__ void mma_f16(float* c, const uint32_t* a, const uint32_t* b) {
    asm volatile(
        "mma.sync.aligned.m16n8k16.row.col.f32.f16.f16.f32 "
        "{%0,%1,%2,%3}, {%4,%5,%6,%7}, {%8,%9}, {%0,%1,%2,%3};"
        : "+f"(c[0]), "+f"(c[1]), "+f"(c[2]), "+f"(c[3])
        : "r"(a[0]), "r"(a[1]), "r"(a[2]), "r"(a[3]), "r"(b[0]), "r"(b[1]));
}
__device__ __forceinline__ __half2 h2(float a, float b) {
    __half2 u; u.x = __float2half_rn(a); u.y = __float2half_rn(b); return u;
}

// tile geometry: 128x128 block tile, BK=64 (128B rows, XOR swizzle)
#define TILE_B  (128*128)          // 16384 B per operand tile
#define STAGE_B (2*TILE_B)         // 32768: A, B
#define STAGES  3
#define SMEMSZ  (STAGES*STAGE_B)   // 98304
#define NTHREADS 128

// one quarter of a stage load: 4 cp16 per thread (j = q*4 .. q*4+3)
#define STAGE_LOADQ(stg_, kc_, q_) do {                                       \
    const size_t k0_ = (size_t)(kc_) << 6;                                    \
    _Pragma("unroll")                                                         \
    for (int j_ = (q_)*4; j_ < (q_)*4 + 4; j_++) {                            \
        int id_  = tid + j_ * NTHREADS;      /* 0..2047 */                    \
        int t_   = id_ >> 10;                                                 \
        int id2_ = id_ & 1023;                                                \
        int row_ = id2_ >> 3;                                                 \
        int ch_  = id2_ & 7;                                                  \
        uint32_t sw_ = (uint32_t)(ch_ ^ (row_ & 7));                          \
        uint32_t sa_ = sb + (uint32_t)(stg_) * STAGE_B + (uint32_t)t_ * TILE_B\
                     + (uint32_t)row_ * 128 + sw_ * 16;                       \
        const __half* src_ = (t_ == 0) ? A : B;                               \
        size_t gr_ = (t_ == 0) ? (bm + row_) : (bn + row_);                   \
        cp16(sa_, src_ + gr_ * (size_t)K + k0_ + ch_ * 8);                    \
    }                                                                         \
} while (0)

// load fragments for one k16 step kkc (0..3) into frag buffer fb
#define FRAG_LOAD(fb_, stbase_, kkc_) do {                                    \
    const uint32_t co_ = ((uint32_t)(((kkc_) << 1) + hiL) ^ rxL) << 4;        \
    _Pragma("unroll")                                                         \
    for (int mt_ = 0; mt_ < 4; ++mt_) {                                       \
        uint32_t ba_ = (stbase_) + aRow + (uint32_t)mt_ * 2048 + co_;         \
        ldsm4(aF[fb_][mt_][0], aF[fb_][mt_][1], aF[fb_][mt_][2], aF[fb_][mt_][3], ba_);\
    }                                                                         \
    _Pragma("unroll")                                                         \
    for (int ng_ = 0; ng_ < 4; ++ng_) {                                       \
        uint32_t bb_ = (stbase_) + TILE_B + bRow + (uint32_t)ng_ * 2048 + co_;\
        uint32_t r0_, r1_, r2_, r3_;                                          \
        ldsm4(r0_, r1_, r2_, r3_, bb_);                                       \
        bF[fb_][2*ng_][0] = r0_;  bF[fb_][2*ng_+1][0] = r1_;                  \
        bF[fb_][2*ng_][1] = r2_;  bF[fb_][2*ng_+1][1] = r3_;                  \
    }                                                                         \
} while (0)

#define MMA32(fb_) do {                                                       \
    _Pragma("unroll")                                                         \
    for (int mt_ = 0; mt_ < 4; ++mt_)                                         \
        _Pragma("unroll")                                                     \
        for (int nt_ = 0; nt_ < 8; ++nt_)                                     \
            mma_f16(acc[mt_][nt_], aF[fb_][mt_], bF[fb_][nt_]);               \
} while (0)

// ---------------------------------------------------------------------------
// GEMM modes:
//   0 = fp32 out + bias p0
//   4 = fused qkv: cols<1024->q, <2048->k, else v^T; biases p0/p1/p2
//   5 = E-scores: exp(alpha*acc) fp16 + row partial sums -> part
//   6 = ctx: acc * alpha / rowsum(part) -> fp16   (reduces part in-kernel)
// ---------------------------------------------------------------------------
template<int OUT>
__global__ __launch_bounds__(NTHREADS, 2)
void mma_gemm(const __half* __restrict__ A, const __half* __restrict__ B,
              const float* __restrict__ p0, const float* __restrict__ p1,
              const float* __restrict__ p2,
              void* __restrict__ O0, void* __restrict__ O1, void* __restrict__ O2,
              float* __restrict__ part,
              int K, int ldC, float alpha,
              long long sA, long long sB, long long sC)
{
    extern __shared__ char smem[];
    const uint32_t sb = s2u(smem);
    const int tid  = threadIdx.x;
    const int lane = tid & 31;
    const int wid  = tid >> 5;             // 0..3
    const int bz   = blockIdx.z;
    const size_t bm = (size_t)blockIdx.y * 128;
    const size_t bn = (size_t)blockIdx.x * 128;

    A += (size_t)bz * sA;  B += (size_t)bz * sB;

    const int wm = (wid & 1) * 64;         // warp M origin
    const int wn = (wid >> 1) * 64;        // warp N origin

    const int lrow = (lane & 7) + ((lane >> 3) & 1) * 8;
    const uint32_t hiL = (uint32_t)((lane >> 4) & 1);
    const uint32_t rxL = (uint32_t)(lrow & 7);
    const uint32_t aRow = (uint32_t)(wm + lrow) * 128;
    const uint32_t bRow = (uint32_t)(wn + lrow) * 128;

    float acc[4][8][4];
#pragma unroll
    for (int i = 0; i < 4; i++)
#pragma unroll
        for (int j = 0; j < 8; j++)
#pragma unroll
            for (int r = 0; r < 4; r++) acc[i][j][r] = 0.0f;

    const int nk = K >> 6;                 // BK=64 chunks (K % 64 == 0 all sites)

    // prologue: stages 0,1 loaded and certified
#pragma unroll
    for (int q = 0; q < 4; ++q) STAGE_LOADQ(0, 0, q);
    asm volatile("cp.async.commit_group;" ::: "memory");
#pragma unroll
    for (int q = 0; q < 4; ++q) STAGE_LOADQ(1, 1, q);
    asm volatile("cp.async.commit_group;" ::: "memory");
    asm volatile("cp.async.wait_group 0;" ::: "memory");
    __syncthreads();

    uint32_t aF[2][4][4], bF[2][8][2];
    FRAG_LOAD(0, sb, 0);                   // chunk0 kk0

    uint32_t sCur = 0, sNxt = 1, sLd = 2;
    for (int kc = 0; kc < nk; ++kc) {
        const bool doLd = (kc + 2 < nk);
        const uint32_t stc = sb + sCur * STAGE_B;
        const uint32_t stn = sb + sNxt * STAGE_B;

        // interleave stage-load quarters between MMA blocks
        if (doLd) STAGE_LOADQ(sLd, kc + 2, 0);
        FRAG_LOAD(1, stc, 1);  MMA32(0);   // kk0
        if (doLd) STAGE_LOADQ(sLd, kc + 2, 1);
        FRAG_LOAD(0, stc, 2);  MMA32(1);   // kk1
        if (doLd) STAGE_LOADQ(sLd, kc + 2, 2);
        FRAG_LOAD(1, stc, 3);  MMA32(0);   // kk2
        if (doLd) STAGE_LOADQ(sLd, kc + 2, 3);
        asm volatile("cp.async.commit_group;" ::: "memory");
        MMA32(1);                          // kk3

        // certify stage kc+1 (group kc+2 may stay in flight)
        asm volatile("cp.async.wait_group 1;" ::: "memory");
        __syncthreads();

        if (kc + 1 < nk) FRAG_LOAD(0, stn, 0);   // next chunk kk0 (certified)

        uint32_t t = sCur; sCur = sNxt; sNxt = sLd; sLd = t;
    }

    // ---- epilogue ----
    const int gid = lane >> 2, tig = lane & 3;

    if (OUT == 0) {
#pragma unroll
        for (int mt = 0; mt < 4; ++mt) {
            const size_t r0 = bm + wm + mt * 16 + gid;
#pragma unroll
            for (int nt = 0; nt < 8; ++nt) {
                const size_t c = bn + wn + nt * 8 + tig * 2;
                float b0 = p0[c], b1 = p0[c + 1];
                float* o = (float*)O0 + (size_t)bz * sC;
                float2 u0; u0.x = acc[mt][nt][0] * alpha + b0;
                           u0.y = acc[mt][nt][1] * alpha + b1;
                float2 u1; u1.x = acc[mt][nt][2] * alpha + b0;
                           u1.y = acc[mt][nt][3] * alpha + b1;
                *(float2*)(o + r0 * (size_t)ldC + c)       = u0;
                *(float2*)(o + (r0 + 8) * (size_t)ldC + c) = u1;
            }
        }
    } else if (OUT == 4) {
        const int sel = (int)(bn >> 10);           // 0=q,1=k,2=v
        const int cb  = (int)(bn & 1023);
        const float* bias = (sel == 0) ? p0 : (sel == 1) ? p1 : p2;
#pragma unroll
        for (int mt = 0; mt < 4; ++mt) {
            const size_t r0 = bm + wm + mt * 16 + gid;
#pragma unroll
            for (int nt = 0; nt < 8; ++nt) {
                const int lc = cb + wn + nt * 8 + tig * 2;
                float b0 = bias[lc], b1 = bias[lc + 1];
                float v00 = acc[mt][nt][0] + b0, v01 = acc[mt][nt][1] + b1;
                float v10 = acc[mt][nt][2] + b0, v11 = acc[mt][nt][3] + b1;
                if (sel < 2) {
                    __half* o = (sel == 0) ? (__half*)O0 : (__half*)O1;
                    *(__half2*)(o + r0 * (size_t)DIM + lc)       = h2(v00, v01);
                    *(__half2*)(o + (r0 + 8) * (size_t)DIM + lc) = h2(v10, v11);
                } else {
                    const int b = (int)(r0 >> 12);
                    const int s0 = (int)(r0 & 4095);
                    __half* o = (__half*)O2 + (size_t)b * DIM * SEQ;
                    o[(size_t)lc * SEQ + s0]           = __float2half_rn(v00);
                    o[(size_t)(lc + 1) * SEQ + s0]     = __float2half_rn(v01);
                    o[(size_t)lc * SEQ + s0 + 8]       = __float2half_rn(v10);
                    o[(size_t)(lc + 1) * SEQ + s0 + 8] = __float2half_rn(v11);
                }
            }
        }
    } else if (OUT == 5) {
        float ps[4][2];
#pragma unroll
        for (int mt = 0; mt < 4; ++mt) { ps[mt][0] = 0.f; ps[mt][1] = 0.f; }
#pragma unroll
        for (int mt = 0; mt < 4; ++mt) {
            const size_t r0 = bm + wm + mt * 16 + gid;
#pragma unroll
            for (int nt = 0; nt < 8; ++nt) {
                const size_t c = bn + wn + nt * 8 + tig * 2;
                float e00 = __expf(fminf(acc[mt][nt][0] * alpha, 11.0f));
                float e01 = __expf(fminf(acc[mt][nt][1] * alpha, 11.0f));
                float e10 = __expf(fminf(acc[mt][nt][2] * alpha, 11.0f));
                float e11 = __expf(fminf(acc[mt][nt][3] * alpha, 11.0f));
                __half* o = (__half*)O0 + (size_t)bz * sC;
                *(__half2*)(o + r0 * (size_t)ldC + c)       = h2(e00, e01);
                *(__half2*)(o + (r0 + 8) * (size_t)ldC + c) = h2(e10, e11);
                ps[mt][0] += e00 + e01;
                ps[mt][1] += e10 + e11;
            }
        }
#pragma unroll
        for (int mt = 0; mt < 4; ++mt)
#pragma unroll
            for (int sr = 0; sr < 2; ++sr) {
                float v = ps[mt][sr];
                v += __shfl_xor_sync(0xffffffffu, v, 1);
                v += __shfl_xor_sync(0xffffffffu, v, 2);
                ps[mt][sr] = v;
            }
        __syncthreads();
        float* buf = (float*)smem;             // [128 rows][2 n-halves]
        const int half = wid >> 1;             // which 64-col half
        if (tig == 0) {
#pragma unroll
            for (int mt = 0; mt < 4; ++mt) {
                buf[(wm + mt * 16 + gid) * 2 + half]     = ps[mt][0];
                buf[(wm + mt * 16 + gid + 8) * 2 + half] = ps[mt][1];
            }
        }
        __syncthreads();
        {
            float t = buf[tid * 2] + buf[tid * 2 + 1];
            part[((size_t)bz * SEQ + bm + tid) * 32 + blockIdx.x] = t;
        }
    } else {  // OUT == 6: reduce part -> inv in smem, then normalize
        __syncthreads();                       // mainloop smem free
        float* invb = (float*)smem;            // [128]
        {
            const float* pp = part + ((size_t)bz * SEQ + bm + tid) * 32;
            float s = 0.0f;
#pragma unroll
            for (int j = 0; j < 32; j++) s += pp[j];
            invb[tid] = 1.0f / s;
        }
        __syncthreads();
#pragma unroll
        for (int mt = 0; mt < 4; ++mt) {
            const int lr0 = wm + mt * 16 + gid;
            const size_t r0 = bm + lr0;
            const float i0 = invb[lr0]     * alpha;
            const float i1 = invb[lr0 + 8] * alpha;
#pragma unroll
            for (int nt = 0; nt < 8; ++nt) {
                const size_t c = bn + wn + nt * 8 + tig * 2;
                __half* o = (__half*)O0 + (size_t)bz * sC;
                *(__half2*)(o + r0 * (size_t)ldC + c) =
                    h2(acc[mt][nt][0] * i0, acc[mt][nt][1] * i0);
                *(__half2*)(o + (r0 + 8) * (size_t)ldC + c) =
                    h2(acc[mt][nt][2] * i1, acc[mt][nt][3] * i1);
            }
        }
    }
}

// ---------------------------------------------------------------------------
// fused casts: y=0 -> x, y>0 -> weights
// ---------------------------------------------------------------------------
__global__ void cast_all_kernel(const float* __restrict__ x,
                                const float* __restrict__ w0, const float* __restrict__ w1,
                                const float* __restrict__ w2, const float* __restrict__ w3,
                                __half* __restrict__ xh, __half* __restrict__ wh)
{
    const int y = blockIdx.y;
    const float* s;
    __half* d;
    int n4;
    if (y == 0) { s = x;  d = xh; n4 = TOK * DIM / 4; }
    else {
        s = (y == 1) ? w0 : (y == 2) ? w1 : (y == 3) ? w2 : w3;
        d = wh + (size_t)(y - 1) * DIM * DIM;
        n4 = DIM * DIM / 4;
    }
    for (int i = blockIdx.x * blockDim.x + threadIdx.x; i < n4;
         i += gridDim.x * blockDim.x) {
        float4 v = ((const float4*)s)[i];
        ((__half2*)d)[i*2+0] = h2(v.x, v.y);
        ((__half2*)d)[i*2+1] = h2(v.z, v.w);
    }
}

// ---------------------------------------------------------------------------
// launch
// ---------------------------------------------------------------------------
extern "C" void kernel_launch(void* const* d_in, const int* in_sizes, int n_in,
                              void* d_out, int out_size)
{
    const float* x  = (const float*)d_in[0];
    const float* Wq = (const float*)d_in[1];
    const float* bq = (const float*)d_in[2];
    const float* Wk = (const float*)d_in[3];
    const float* bk = (const float*)d_in[4];
    const float* Wv = (const float*)d_in[5];
    const float* bv = (const float*)d_in[6];
    const float* Wo = (const float*)d_in[7];
    const float* bo = (const float*)d_in[8];
    float* out = (float*)d_out;

    __half *xh, *qh, *kh, *vth, *ch, *eh, *w;
    float *part;
    cudaGetSymbolAddress((void**)&xh,   g_x);
    cudaGetSymbolAddress((void**)&qh,   g_q);
    cudaGetSymbolAddress((void**)&kh,   g_k);
    cudaGetSymbolAddress((void**)&vth,  g_vt);
    cudaGetSymbolAddress((void**)&ch,   g_c);
    cudaGetSymbolAddress((void**)&eh,   g_e);
    cudaGetSymbolAddress((void**)&w,    g_w);
    cudaGetSymbolAddress((void**)&part, g_part);

    cudaFuncSetAttribute(mma_gemm<0>, cudaFuncAttributeMaxDynamicSharedMemorySize, SMEMSZ);
    cudaFuncSetAttribute(mma_gemm<4>, cudaFuncAttributeMaxDynamicSharedMemorySize, SMEMSZ);
    cudaFuncSetAttribute(mma_gemm<5>, cudaFuncAttributeMaxDynamicSharedMemorySize, SMEMSZ);
    cudaFuncSetAttribute(mma_gemm<6>, cudaFuncAttributeMaxDynamicSharedMemorySize, SMEMSZ);

    const long long sX = (long long)SEQ * DIM;
    const long long sT = (long long)DIM * SEQ;
    const long long sS = (long long)SEQ * SEQ;

    // fused casts (x + 4 weight matrices), one launch
    {
        dim3 g(4096, 5);
        cast_all_kernel<<<g, 256>>>(x, Wq, Wk, Wv, Wo, xh, w);
    }

    // fused qkv projection: [16384 x 3072] = x @ [Wq;Wk;Wv]^T
    {
        dim3 g(3 * DIM / 128, TOK / 128, 1);
        mma_gemm<4><<<g, NTHREADS, SMEMSZ>>>(xh, w, bq, bk, bv,
                                             qh, kh, vth, nullptr,
                                             DIM, DIM, 1.0f, 0, 0, 0);
    }

    // E = exp(SCALE * q @ k^T), fp16, + row partial sums
    {
        dim3 g(SEQ / 128, SEQ / 128, BATCH);
        mma_gemm<5><<<g, NTHREADS, SMEMSZ>>>(qh, kh, nullptr, nullptr, nullptr,
                                             eh, nullptr, nullptr, part,
                                             DIM, SEQ, SCALE, sX, sX, sS);
    }

    // ctx' = 32 * (E @ v) / rowsum   (partials reduced in epilogue)
    {
        dim3 g(DIM / 128, SEQ / 128, BATCH);
        mma_gemm<6><<<g, NTHREADS, SMEMSZ>>>(eh, vth, nullptr, nullptr, nullptr,
                                             ch, nullptr, nullptr, part,
                                             SEQ, DIM, 32.0f, sS, sT, sX);
    }

    // out = (ctx' @ Wo^T)/32 + bo
    {
        dim3 g(DIM / 128, TOK / 128, 1);
        mma_gemm<0><<<g, NTHREADS, SMEMSZ>>>(ch, w + 3ll * DIM * DIM, bo, nullptr, nullptr,
                                             out, nullptr, nullptr, nullptr,
                                             DIM, DIM, 0.03125f, 0, 0, 0);
    }
}